// round 10
// baseline (speedup 1.0000x reference)
#include <cuda_runtime.h>

typedef unsigned long long u64;

static __device__ __forceinline__ u64 pk2(float lo, float hi) {
    u64 r; asm("mov.b64 %0,{%1,%2};" : "=l"(r) : "f"(lo), "f"(hi)); return r;
}
static __device__ __forceinline__ void unpk(u64 v, float &lo, float &hi) {
    asm("mov.b64 {%0,%1}, %2;" : "=f"(lo), "=f"(hi) : "l"(v));
}
static __device__ __forceinline__ void ffma2(u64 &d, u64 a, u64 b) {
    asm("fma.rn.f32x2 %0, %1, %2, %0;" : "+l"(d) : "l"(a), "l"(b));
}

// ------------------------------ scratch ------------------------------------
__device__ float g_A2[8 * 32 * 32 * 384];      // blocks (s1,s2,s3,d12,d13,d23)
__device__ float g_A1[8 * 32 * 640];           // a1 [B,n,10C]
__device__ float g_A0[8 * 320];                // a0 [B,5C]
__device__ float g_R12 [3 * 8 * 32 * 64];      // a1@W12[i]+b12[i]   (by t)
__device__ float g_R12t[3 * 8 * 32 * 64];      // a1@W12t[i]+b12t[i] (by d)
__device__ float g_R02b[3 * 8 * 64];           // a0@W02[i]+b02[i]+b22[i]
__device__ float g_Rmd [8 * 32 * 64];          // a1@W11+b11 + a0@W01+b01
__device__ float g_S[3 * 8 * 32 * 32 * 64];    // slices [i][b][t][d][64]

// ----------------- K1: second-order contractions into A2 --------------------
// grid (256, 3): x = b*32+P.  y=0: s1; y=1: s2+s3 fused single pass; y=2: diags.
__global__ void k_contract(const float* __restrict__ x) {
    const int y = blockIdx.y;
    const int b = blockIdx.x >> 5, P = blockIdx.x & 31;
    const int tid = threadIdx.x;
    const float* xb = x + b * 2097152;
    if (y == 0) {
#pragma unroll
        for (int r = 0; r < 8; r++) {
            const int idx = r * 256 + tid;
            const int e = idx >> 6, c = idx & 63;
            const float* p = xb + P * 2048 + e * 64 + c;
            float s = 0.f;
#pragma unroll
            for (int i = 0; i < 32; i++) s += p[i * 65536];
            g_A2[((b * 32 + P) * 32 + e) * 384 + 0 + c] = s * 0.03125f;
        }
    } else if (y == 1) {
        __shared__ float ps3[4 * 32 * 64];
        const int c = tid & 63, qs = tid >> 6;
        float s2acc[8] = {0, 0, 0, 0, 0, 0, 0, 0};
        const float* base = xb + P * 65536;
        for (int j = 0; j < 32; j++) {
            float t = 0.f;
#pragma unroll
            for (int kk = 0; kk < 8; kk++) {
                const int k = qs + kk * 4;
                const float v = base[j * 2048 + k * 64 + c];
                s2acc[kk] += v; t += v;
            }
            ps3[(qs * 32 + j) * 64 + c] = t;
        }
        __syncthreads();
#pragma unroll
        for (int kk = 0; kk < 8; kk++) {
            const int k = qs + kk * 4;
            g_A2[((b * 32 + P) * 32 + k) * 384 + 64 + c] = s2acc[kk] * 0.03125f;
        }
        for (int idx = tid; idx < 2048; idx += 256) {
            const int j = idx >> 6, cc = idx & 63;
            const float s = ps3[j * 64 + cc] + ps3[2048 + j * 64 + cc]
                          + ps3[4096 + j * 64 + cc] + ps3[6144 + j * 64 + cc];
            g_A2[((b * 32 + P) * 32 + j) * 384 + 128 + cc] = s * 0.03125f;
        }
    } else {
        for (int idx = tid; idx < 6144; idx += 256) {
            const int kind = idx >> 11;
            const int e = (idx >> 6) & 31, c = idx & 63;
            float v;
            if (kind == 0)      v = xb[e * 65536 + e * 2048 + P * 64 + c];
            else if (kind == 1) v = xb[e * 65536 + P * 2048 + e * 64 + c];
            else                v = xb[P * 65536 + e * 2048 + e * 64 + c];
            g_A2[((b * 32 + P) * 32 + e) * 384 + (3 + kind) * 64 + c] = v;
        }
    }
}

// ----------------- K2: a1 from A2. grid (8, 10), 256 threads ----------------
__global__ void k_a1() {
    const int b = blockIdx.x, blk = blockIdx.y;
    const int tid = threadIdx.x;
    const int t = tid >> 3, c0 = (tid & 7) * 8;
    int off, axis;
    switch (blk) {
        case 0: off = 0;   axis = 0; break;
        case 1: off = 0;   axis = 1; break;
        case 2: off = 64;  axis = 1; break;
        case 3: off = 192; axis = 0; break;
        case 4: off = 192; axis = 1; break;
        case 5: off = 256; axis = 0; break;
        case 6: off = 256; axis = 1; break;
        case 7: off = 320; axis = 0; break;
        case 8: off = 320; axis = 1; break;
        default: off = 320; axis = 2; break;
    }
#pragma unroll
    for (int e = 0; e < 8; e++) {
        const int c = c0 + e;
        float s = 0.f;
        if (axis == 2) {
            s = g_A2[((b * 32 + t) * 32 + t) * 384 + off + c];
        } else if (axis == 0) {
            for (int p = 0; p < 32; p++) s += g_A2[((b * 32 + p) * 32 + t) * 384 + off + c];
            s *= 0.03125f;
        } else {
            for (int q = 0; q < 32; q++) s += g_A2[((b * 32 + t) * 32 + q) * 384 + off + c];
            s *= 0.03125f;
        }
        g_A1[(b * 32 + t) * 640 + blk * 64 + c] = s;
    }
}

// ----------------- K2b: a0 from a1. grid 8, 256 threads ---------------------
__global__ void k_a0() {
    const int b = blockIdx.x;
    const int srcmap[5] = {2, 4, 6, 8, 9};
    for (int idx = threadIdx.x; idx < 320; idx += 256) {
        const int blk = idx >> 6, c = idx & 63;
        const int so = srcmap[blk] * 64 + c;
        float s = 0.f;
        for (int t = 0; t < 32; t++) s += g_A1[(b * 32 + t) * 640 + so];
        g_A0[b * 320 + idx] = s * 0.03125f;
    }
}

// ----------------- K4: vector mixes. grid (32, 7), 256 threads --------------
// Each block: 8 a1 rows (one row-group g), W element reused across 8 rows.
// y<3: R12[i=y]; y<6: R12t[i=y-3]; y==6: Rmd (+R02b when g%4==0).
__global__ void k_vec(const float* __restrict__ W12, const float* __restrict__ b12,
                      const float* __restrict__ W12t, const float* __restrict__ b12t,
                      const float* __restrict__ W02, const float* __restrict__ b02,
                      const float* __restrict__ W11, const float* __restrict__ b11,
                      const float* __restrict__ W01, const float* __restrict__ b01,
                      const float* __restrict__ b22) {
    __shared__ float a1sh[8][640];
    __shared__ float a0sh[320];
    __shared__ float psum[4][8][64];
    __shared__ float psumA0[4][64];
    __shared__ float psum2[4][3][64];
    const int g = blockIdx.x;              // rows g*8 .. g*8+7 (same batch)
    const int y = blockIdx.y;
    const int tid = threadIdx.x;
    const int o = tid & 63, chunk = tid >> 6;
    const int b = g >> 2;
    const int row0 = g * 8;

    for (int idx = tid; idx < 5120; idx += 256) {
        const int r = idx / 640, k = idx - r * 640;
        a1sh[r][k] = g_A1[(row0 + r) * 640 + k];
    }
    if (y == 6) for (int idx = tid; idx < 320; idx += 256) a0sh[idx] = g_A0[b * 320 + idx];
    __syncthreads();

    const float* W;
    if (y < 3)      W = W12  + y * 40960;
    else if (y < 6) W = W12t + (y - 3) * 40960;
    else            W = W11;

    float acc[8] = {0.f, 0.f, 0.f, 0.f, 0.f, 0.f, 0.f, 0.f};
    const int k0 = chunk * 160;
#pragma unroll 4
    for (int k = k0; k < k0 + 160; k++) {
        const float w = __ldg(W + k * 64 + o);
#pragma unroll
        for (int r = 0; r < 8; r++) acc[r] += a1sh[r][k] * w;
    }
#pragma unroll
    for (int r = 0; r < 8; r++) psum[chunk][r][o] = acc[r];

    if (y == 6) {
        float a0acc = 0.f;
        const int ka = chunk * 80;
#pragma unroll 4
        for (int k = ka; k < ka + 80; k++)
            a0acc += a0sh[k] * __ldg(W01 + k * 64 + o);
        psumA0[chunk][o] = a0acc;
        if ((g & 3) == 0) {
            float s0 = 0.f, s1 = 0.f, s2v = 0.f;
#pragma unroll 4
            for (int k = ka; k < ka + 80; k++) {
                const float a = a0sh[k];
                s0  += a * __ldg(W02 + 0 * 20480 + k * 64 + o);
                s1  += a * __ldg(W02 + 1 * 20480 + k * 64 + o);
                s2v += a * __ldg(W02 + 2 * 20480 + k * 64 + o);
            }
            psum2[chunk][0][o] = s0; psum2[chunk][1][o] = s1; psum2[chunk][2][o] = s2v;
        }
    }
    __syncthreads();

    for (int idx = tid; idx < 512; idx += 256) {
        const int r = idx >> 6, oo = idx & 63;
        float s = psum[0][r][oo] + psum[1][r][oo] + psum[2][r][oo] + psum[3][r][oo];
        const int row = row0 + r;
        if (y < 3) {
            s += __ldg(b12 + y * 64 + oo);
            g_R12[(y * 256 + row) * 64 + oo] = s;
        } else if (y < 6) {
            s += __ldg(b12t + (y - 3) * 64 + oo);
            g_R12t[((y - 3) * 256 + row) * 64 + oo] = s;
        } else {
            s += psumA0[0][oo] + psumA0[1][oo] + psumA0[2][oo] + psumA0[3][oo]
               + __ldg(b11 + oo) + __ldg(b01 + oo);
            g_Rmd[row * 64 + oo] = s;
        }
    }
    if (y == 6 && (g & 3) == 0) {
        for (int idx = tid; idx < 192; idx += 256) {
            const int i = idx >> 6, oo = idx & 63;
            const float s2 = psum2[0][i][oo] + psum2[1][i][oo] + psum2[2][i][oo] + psum2[3][i][oo]
                           + __ldg(b02 + i * 64 + oo) + __ldg(b22 + i * 64 + oo);
            g_R02b[(i * 8 + b) * 64 + oo] = s2;
        }
    }
}

// ----------------- K3: main GEMM  T = allp @ W33 + b33 ----------------------
// grid 148 persistent, 256 threads. smem: wsh[384*64] + 2 x xsh[384*33] = 199.7KB.
// W read as ulonglong2 (LDS.128 broadcast): 2 crossbar passes/warp/cc for W.
__global__ void k_main(const float* __restrict__ x, const float* __restrict__ W33,
                       const float* __restrict__ b33, float* __restrict__ out) {
    extern __shared__ float sm[];
    float* wsh  = sm;                   // 24576
    float* xshA = sm + 24576;           // 12672
    float* xshB = sm + 24576 + 12672;   // 12672
    const int tid = threadIdx.x;
    const int warp = tid >> 5, lane = tid & 31;
    const int o0 = warp * 8;

    const float4* W4 = (const float4*)W33;
    float4* wsh4 = (float4*)wsh;
    for (int idx = tid; idx < 6144; idx += 256) wsh4[idx] = W4[idx];

    const float4* x4 = (const float4*)x;
    float4* out4 = (float4*)out;

    const float bb0 = __ldg(b33 + o0 + 0), bb1 = __ldg(b33 + o0 + 1);
    const float bb2 = __ldg(b33 + o0 + 2), bb3 = __ldg(b33 + o0 + 3);
    const float bb4 = __ldg(b33 + o0 + 4), bb5 = __ldg(b33 + o0 + 5);
    const float bb6 = __ldg(b33 + o0 + 6), bb7 = __ldg(b33 + o0 + 7);

    __syncthreads();

    for (int pair = blockIdx.x; pair < 4096; pair += gridDim.x) {
        const int pen0 = pair * 2;
        const int b = pen0 >> 10, i = (pen0 >> 5) & 31, j0 = pen0 & 31;
        for (int idx = tid; idx < 6144; idx += 256) {
            const int half = idx / 3072;
            const int id2 = idx - half * 3072;
            const int p = id2 >> 9, rem = id2 & 511, k = rem >> 4, c4 = rem & 15;
            const int j = j0 + half;
            int A, B, C;
            switch (p) {
                case 0: A = i; B = j; C = k; break;
                case 1: A = i; B = k; C = j; break;
                case 2: A = j; B = i; C = k; break;
                case 3: A = k; B = i; C = j; break;
                case 4: A = j; B = k; C = i; break;
                default: A = k; B = j; C = i; break;
            }
            const float4 v = x4[b * 524288 + A * 16384 + B * 512 + C * 16 + c4];
            float* xs = half ? xshB : xshA;
            const int cc = p * 64 + c4 * 4;
            xs[(cc + 0) * 33 + k] = v.x;
            xs[(cc + 1) * 33 + k] = v.y;
            xs[(cc + 2) * 33 + k] = v.z;
            xs[(cc + 3) * 33 + k] = v.w;
        }
        __syncthreads();

        u64 aA0 = pk2(bb0, bb1), aA1 = pk2(bb2, bb3);
        u64 aA2 = pk2(bb4, bb5), aA3 = pk2(bb6, bb7);
        u64 aB0 = aA0, aB1 = aA1, aB2 = aA2, aB3 = aA3;
#pragma unroll 4
        for (int cc = 0; cc < 384; cc++) {
            const ulonglong2* wr = (const ulonglong2*)(wsh + cc * 64 + o0);
            const ulonglong2 wv0 = wr[0];
            const ulonglong2 wv1 = wr[1];
            const float xa  = xshA[cc * 33 + lane];
            const float xb_ = xshB[cc * 33 + lane];
            const u64 xa2 = pk2(xa, xa);
            const u64 xb2 = pk2(xb_, xb_);
            ffma2(aA0, xa2, wv0.x); ffma2(aA1, xa2, wv0.y);
            ffma2(aA2, xa2, wv1.x); ffma2(aA3, xa2, wv1.y);
            ffma2(aB0, xb2, wv0.x); ffma2(aB1, xb2, wv0.y);
            ffma2(aB2, xb2, wv1.x); ffma2(aB3, xb2, wv1.y);
        }
        float4 r0, r1;
        unpk(aA0, r0.x, r0.y); unpk(aA1, r0.z, r0.w);
        unpk(aA2, r1.x, r1.y); unpk(aA3, r1.z, r1.w);
        int ob = pen0 * 512 + lane * 16 + (o0 >> 2);
        out4[ob] = r0; out4[ob + 1] = r1;
        unpk(aB0, r0.x, r0.y); unpk(aB1, r0.z, r0.w);
        unpk(aB2, r1.x, r1.y); unpk(aB3, r1.z, r1.w);
        ob += 512;
        out4[ob] = r0; out4[ob + 1] = r1;
        __syncthreads();
    }
}

// ----------------- K5: slice GEMM  slices[i] = a2wt @ W22[i] + terms --------
// grid 768 (i*256 + b*32 + t), 256 threads, 149KB dyn smem.
__global__ void k_slice(const float* __restrict__ W22) {
    extern __shared__ float sm[];
    float* wsh = sm;
    float* ash = sm + 24576;
    const int bid = blockIdx.x;
    const int i = bid >> 8, b = (bid >> 5) & 7, t = bid & 31;
    const int tid = threadIdx.x;
    const int warp = tid >> 5, lane = tid & 31;
    const int o0 = warp * 8;

    float bo[8];
#pragma unroll
    for (int e = 0; e < 8; e++) {
        const int o = o0 + e;
        bo[e] = g_R12[((i * 8 + b) * 32 + t) * 64 + o]
              + g_R12t[((i * 8 + b) * 32 + lane) * 64 + o]
              + g_R02b[(i * 8 + b) * 64 + o];
    }
    u64 acc0 = pk2(bo[0], bo[1]), acc1 = pk2(bo[2], bo[3]);
    u64 acc2 = pk2(bo[4], bo[5]), acc3 = pk2(bo[6], bo[7]);

    const float4* W4 = (const float4*)(W22 + i * 49152);
    const float4* A24 = (const float4*)g_A2;

    for (int tile = 0; tile < 2; tile++) {
        for (int idx = tid; idx < 6144; idx += 256)
            ((float4*)wsh)[idx] = W4[tile * 6144 + idx];
        for (int idx = tid; idx < 3072; idx += 256) {
            const int d = idx / 96, c4 = idx % 96;
            const int P = tile ? d : t, Q = tile ? t : d;
            const float4 v = A24[((b * 32 + P) * 32 + Q) * 96 + c4];
            const int cc = c4 * 4;
            ash[(cc + 0) * 33 + d] = v.x;
            ash[(cc + 1) * 33 + d] = v.y;
            ash[(cc + 2) * 33 + d] = v.z;
            ash[(cc + 3) * 33 + d] = v.w;
        }
        __syncthreads();
#pragma unroll 4
        for (int cc = 0; cc < 384; cc++) {
            const ulonglong2* wr = (const ulonglong2*)(wsh + cc * 64 + o0);
            const ulonglong2 wv0 = wr[0];
            const ulonglong2 wv1 = wr[1];
            const float xv = ash[cc * 33 + lane];
            const u64 xx = pk2(xv, xv);
            ffma2(acc0, xx, wv0.x); ffma2(acc1, xx, wv0.y);
            ffma2(acc2, xx, wv1.x); ffma2(acc3, xx, wv1.y);
        }
        __syncthreads();
    }
    float4 r0, r1;
    unpk(acc0, r0.x, r0.y); unpk(acc1, r0.z, r0.w);
    unpk(acc2, r1.x, r1.y); unpk(acc3, r1.z, r1.w);
    float4* S4 = (float4*)g_S;
    const int ob = (((i * 8 + b) * 32 + t) * 32 + lane) * 16 + (o0 >> 2);
    S4[ob] = r0; S4[ob + 1] = r1;
}

// ----------------- K6: diagonal scatter-add. grid 256, 256 threads ----------
__global__ void k_scatter(float* __restrict__ out) {
    const int bt = blockIdx.x;
    const int b = bt >> 5, t = bt & 31;
    const int tid = threadIdx.x;
    const int dg = tid >> 6, c = tid & 63;
    const float* S0 = g_S + ((0 * 8 + b) * 32 + t) * 2048;
    const float* S1 = g_S + ((1 * 8 + b) * 32 + t) * 2048;
    const float* S2 = g_S + ((2 * 8 + b) * 32 + t) * 2048;
    float* ob = out + b * 2097152;
    for (int d = dg; d < 32; d += 4) {
        const float s0 = S0[d * 64 + c], s1 = S1[d * 64 + c], s2 = S2[d * 64 + c];
        if (d != t) {
            ob[d * 65536 + d * 2048 + t * 64 + c] += s0;   // T[b,d,d,t]
            ob[d * 65536 + t * 2048 + d * 64 + c] += s1;   // T[b,d,t,d]
            ob[t * 65536 + d * 2048 + d * 64 + c] += s2;   // T[b,t,d,d]
        } else {
            ob[d * 65536 + d * 2048 + d * 64 + c] += s0 + s1 + s2 + g_Rmd[(b * 32 + d) * 64 + c];
        }
    }
}

// ---------------------------------------------------------------------------
extern "C" void kernel_launch(void* const* d_in, const int* in_sizes, int n_in,
                              void* d_out, int out_size) {
    const float* x    = (const float*)d_in[0];
    const float* W33  = (const float*)d_in[1];
    const float* b33  = (const float*)d_in[2];
    const float* W22  = (const float*)d_in[3];
    const float* b22  = (const float*)d_in[4];
    const float* W12  = (const float*)d_in[5];
    const float* b12  = (const float*)d_in[6];
    const float* W12t = (const float*)d_in[7];
    const float* b12t = (const float*)d_in[8];
    const float* W02  = (const float*)d_in[9];
    const float* b02  = (const float*)d_in[10];
    const float* W11  = (const float*)d_in[11];
    const float* b11  = (const float*)d_in[12];
    const float* W01  = (const float*)d_in[13];
    const float* b01  = (const float*)d_in[14];
    float* out = (float*)d_out;

    const size_t sm_main  = (24576 + 2 * 384 * 33) * sizeof(float);  // 199680
    const size_t sm_slice = (24576 + 384 * 33) * sizeof(float);      // 148992
    cudaFuncSetAttribute(k_main,  cudaFuncAttributeMaxDynamicSharedMemorySize, (int)sm_main);
    cudaFuncSetAttribute(k_slice, cudaFuncAttributeMaxDynamicSharedMemorySize, (int)sm_slice);

    k_contract<<<dim3(256, 3), 256>>>(x);
    k_a1<<<dim3(8, 10), 256>>>();
    k_a0<<<8, 256>>>();
    k_vec<<<dim3(32, 7), 256>>>(W12, b12, W12t, b12t, W02, b02, W11, b11, W01, b01, b22);
    k_main<<<148, 256, sm_main>>>(x, W33, b33, out);
    k_slice<<<768, 256, sm_slice>>>(W22);
    k_scatter<<<256, 256>>>(out);
}

// round 11
// speedup vs baseline: 1.0264x; 1.0264x over previous
#include <cuda_runtime.h>

typedef unsigned long long u64;

static __device__ __forceinline__ u64 pk2(float lo, float hi) {
    u64 r; asm("mov.b64 %0,{%1,%2};" : "=l"(r) : "f"(lo), "f"(hi)); return r;
}
static __device__ __forceinline__ void unpk(u64 v, float &lo, float &hi) {
    asm("mov.b64 {%0,%1}, %2;" : "=f"(lo), "=f"(hi) : "l"(v));
}
static __device__ __forceinline__ void ffma2(u64 &d, u64 a, u64 b) {
    asm("fma.rn.f32x2 %0, %1, %2, %0;" : "+l"(d) : "l"(a), "l"(b));
}

// ------------------------------ scratch ------------------------------------
__device__ float g_A2[8 * 32 * 32 * 384];      // blocks (s1,s2,s3,d12,d13,d23)
__device__ float g_A1[8 * 32 * 640];           // a1 [B,n,10C]
__device__ float g_A0[8 * 320];                // a0 [B,5C]
__device__ float g_R12 [3 * 8 * 32 * 64];      // a1@W12[i]+b12[i]   (by t)
__device__ float g_R12t[3 * 8 * 32 * 64];      // a1@W12t[i]+b12t[i] (by d)
__device__ float g_R02b[3 * 8 * 64];           // a0@W02[i]+b02[i]+b22[i]
__device__ float g_Rmd [8 * 32 * 64];          // a1@W11+b11 + a0@W01+b01
__device__ float g_S[3 * 8 * 32 * 32 * 64];    // slices [i][b][t][d][64]

// ----------------- K1: second-order contractions into A2 --------------------
// grid (256, 3): x = b*32+P.  y=0: s1; y=1: s2+s3 fused single pass; y=2: diags.
__global__ void k_contract(const float* __restrict__ x) {
    const int y = blockIdx.y;
    const int b = blockIdx.x >> 5, P = blockIdx.x & 31;
    const int tid = threadIdx.x;
    const float* xb = x + b * 2097152;
    if (y == 0) {
#pragma unroll
        for (int r = 0; r < 8; r++) {
            const int idx = r * 256 + tid;
            const int e = idx >> 6, c = idx & 63;
            const float* p = xb + P * 2048 + e * 64 + c;
            float s = 0.f;
#pragma unroll
            for (int i = 0; i < 32; i++) s += p[i * 65536];
            g_A2[((b * 32 + P) * 32 + e) * 384 + 0 + c] = s * 0.03125f;
        }
    } else if (y == 1) {
        __shared__ float ps3[4 * 32 * 64];
        const int c = tid & 63, qs = tid >> 6;
        float s2acc[8] = {0, 0, 0, 0, 0, 0, 0, 0};
        const float* base = xb + P * 65536;
        for (int j = 0; j < 32; j++) {
            float t = 0.f;
#pragma unroll
            for (int kk = 0; kk < 8; kk++) {
                const int k = qs + kk * 4;
                const float v = base[j * 2048 + k * 64 + c];
                s2acc[kk] += v; t += v;
            }
            ps3[(qs * 32 + j) * 64 + c] = t;
        }
        __syncthreads();
#pragma unroll
        for (int kk = 0; kk < 8; kk++) {
            const int k = qs + kk * 4;
            g_A2[((b * 32 + P) * 32 + k) * 384 + 64 + c] = s2acc[kk] * 0.03125f;
        }
        for (int idx = tid; idx < 2048; idx += 256) {
            const int j = idx >> 6, cc = idx & 63;
            const float s = ps3[j * 64 + cc] + ps3[2048 + j * 64 + cc]
                          + ps3[4096 + j * 64 + cc] + ps3[6144 + j * 64 + cc];
            g_A2[((b * 32 + P) * 32 + j) * 384 + 128 + cc] = s * 0.03125f;
        }
    } else {
        for (int idx = tid; idx < 6144; idx += 256) {
            const int kind = idx >> 11;
            const int e = (idx >> 6) & 31, c = idx & 63;
            float v;
            if (kind == 0)      v = xb[e * 65536 + e * 2048 + P * 64 + c];
            else if (kind == 1) v = xb[e * 65536 + P * 2048 + e * 64 + c];
            else                v = xb[P * 65536 + e * 2048 + e * 64 + c];
            g_A2[((b * 32 + P) * 32 + e) * 384 + (3 + kind) * 64 + c] = v;
        }
    }
}

// ----------------- K2: a1 from A2. grid (8, 10), 256 threads ----------------
__global__ void k_a1() {
    const int b = blockIdx.x, blk = blockIdx.y;
    const int tid = threadIdx.x;
    const int t = tid >> 3, c0 = (tid & 7) * 8;
    int off, axis;
    switch (blk) {
        case 0: off = 0;   axis = 0; break;
        case 1: off = 0;   axis = 1; break;
        case 2: off = 64;  axis = 1; break;
        case 3: off = 192; axis = 0; break;
        case 4: off = 192; axis = 1; break;
        case 5: off = 256; axis = 0; break;
        case 6: off = 256; axis = 1; break;
        case 7: off = 320; axis = 0; break;
        case 8: off = 320; axis = 1; break;
        default: off = 320; axis = 2; break;
    }
#pragma unroll
    for (int e = 0; e < 8; e++) {
        const int c = c0 + e;
        float s = 0.f;
        if (axis == 2) {
            s = g_A2[((b * 32 + t) * 32 + t) * 384 + off + c];
        } else if (axis == 0) {
            for (int p = 0; p < 32; p++) s += g_A2[((b * 32 + p) * 32 + t) * 384 + off + c];
            s *= 0.03125f;
        } else {
            for (int q = 0; q < 32; q++) s += g_A2[((b * 32 + t) * 32 + q) * 384 + off + c];
            s *= 0.03125f;
        }
        g_A1[(b * 32 + t) * 640 + blk * 64 + c] = s;
    }
}

// ----------------- K2b: a0 from a1. grid 8, 256 threads ---------------------
__global__ void k_a0() {
    const int b = blockIdx.x;
    const int srcmap[5] = {2, 4, 6, 8, 9};
    for (int idx = threadIdx.x; idx < 320; idx += 256) {
        const int blk = idx >> 6, c = idx & 63;
        const int so = srcmap[blk] * 64 + c;
        float s = 0.f;
        for (int t = 0; t < 32; t++) s += g_A1[(b * 32 + t) * 640 + so];
        g_A0[b * 320 + idx] = s * 0.03125f;
    }
}

// ----------------- K4: vector mixes. grid (256, 7), 256 threads -------------
// (R9 version: one row per block, high occupancy — measured 48.7us)
__global__ void k_vec(const float* __restrict__ W12, const float* __restrict__ b12,
                      const float* __restrict__ W12t, const float* __restrict__ b12t,
                      const float* __restrict__ W02, const float* __restrict__ b02,
                      const float* __restrict__ W11, const float* __restrict__ b11,
                      const float* __restrict__ W01, const float* __restrict__ b01,
                      const float* __restrict__ b22) {
    __shared__ float a1sh[640];
    __shared__ float a0sh[320];
    __shared__ float psum[4][64];
    __shared__ float psum2[4][64];
    const int row = blockIdx.x;            // b*32 + t
    const int y = blockIdx.y;
    const int tid = threadIdx.x;
    const int o = tid & 63, chunk = tid >> 6;
    const int b = row >> 5, t = row & 31;

    for (int idx = tid; idx < 640; idx += 256) a1sh[idx] = g_A1[row * 640 + idx];
    if (y == 6) for (int idx = tid; idx < 320; idx += 256) a0sh[idx] = g_A0[b * 320 + idx];
    __syncthreads();

    const float* W; float* dst;
    if (y < 3)      { W = W12  + y * 40960;        dst = g_R12  + (y * 256 + row) * 64; }
    else if (y < 6) { W = W12t + (y - 3) * 40960;  dst = g_R12t + ((y - 3) * 256 + row) * 64; }
    else            { W = W11;                     dst = g_Rmd + row * 64; }

    float acc = 0.f;
    const int k0 = chunk * 160;
#pragma unroll 8
    for (int k = k0; k < k0 + 160; k++)
        acc += a1sh[k] * __ldg(W + k * 64 + o);
    if (y == 6) {
#pragma unroll 8
        for (int k = chunk * 80; k < chunk * 80 + 80; k++)
            acc += a0sh[k] * __ldg(W01 + k * 64 + o);
    }
    psum[chunk][o] = acc;

    if (y == 6 && t < 3) {
        float acc2 = 0.f;
#pragma unroll 8
        for (int k = chunk * 80; k < chunk * 80 + 80; k++)
            acc2 += a0sh[k] * __ldg(W02 + t * 20480 + k * 64 + o);
        psum2[chunk][o] = acc2;
    }
    __syncthreads();
    if (chunk == 0) {
        float s = psum[0][o] + psum[1][o] + psum[2][o] + psum[3][o];
        if (y < 3)      s += __ldg(b12  + y * 64 + o);
        else if (y < 6) s += __ldg(b12t + (y - 3) * 64 + o);
        else            s += __ldg(b11 + o) + __ldg(b01 + o);
        dst[o] = s;
        if (y == 6 && t < 3) {
            float s2 = psum2[0][o] + psum2[1][o] + psum2[2][o] + psum2[3][o]
                     + __ldg(b02 + t * 64 + o) + __ldg(b22 + t * 64 + o);
            g_R02b[(t * 8 + b) * 64 + o] = s2;
        }
    }
}

// ----------------- K3: main GEMM  T = allp @ W33 + b33 ----------------------
// grid 148 persistent, 512 threads (16 warps, 4/SMSP for latency hiding).
// Warps 0-7: pencil A channels warp*8; warps 8-15: pencil B, same channels.
// smem: wsh[384*64] + 2 x xsh[384*33] = 199.7KB.
__global__ void k_main(const float* __restrict__ x, const float* __restrict__ W33,
                       const float* __restrict__ b33, float* __restrict__ out) {
    extern __shared__ float sm[];
    float* wsh  = sm;                   // 24576
    float* xshA = sm + 24576;           // 12672
    float* xshB = sm + 24576 + 12672;   // 12672
    const int tid = threadIdx.x;
    const int warp = tid >> 5, lane = tid & 31;
    const int half = warp >> 3;         // 0: pencil A, 1: pencil B
    const int o0 = (warp & 7) * 8;
    const float* xs = half ? xshB : xshA;

    const float4* W4 = (const float4*)W33;
    float4* wsh4 = (float4*)wsh;
    for (int idx = tid; idx < 6144; idx += 512) wsh4[idx] = W4[idx];

    const float4* x4 = (const float4*)x;
    float4* out4 = (float4*)out;

    const float bb0 = __ldg(b33 + o0 + 0), bb1 = __ldg(b33 + o0 + 1);
    const float bb2 = __ldg(b33 + o0 + 2), bb3 = __ldg(b33 + o0 + 3);
    const float bb4 = __ldg(b33 + o0 + 4), bb5 = __ldg(b33 + o0 + 5);
    const float bb6 = __ldg(b33 + o0 + 6), bb7 = __ldg(b33 + o0 + 7);

    __syncthreads();

    for (int pair = blockIdx.x; pair < 4096; pair += gridDim.x) {
        const int pen0 = pair * 2;
        const int b = pen0 >> 10, i = (pen0 >> 5) & 31, j0 = pen0 & 31;
        // stage 6 permutation pencils for both pencils (j0, j0+1)
        for (int idx = tid; idx < 6144; idx += 512) {
            const int h = idx / 3072;
            const int id2 = idx - h * 3072;
            const int p = id2 >> 9, rem = id2 & 511, k = rem >> 4, c4 = rem & 15;
            const int j = j0 + h;
            int A, B, C;
            switch (p) {
                case 0: A = i; B = j; C = k; break;
                case 1: A = i; B = k; C = j; break;
                case 2: A = j; B = i; C = k; break;
                case 3: A = k; B = i; C = j; break;
                case 4: A = j; B = k; C = i; break;
                default: A = k; B = j; C = i; break;
            }
            const float4 v = x4[b * 524288 + A * 16384 + B * 512 + C * 16 + c4];
            float* dst = h ? xshB : xshA;
            const int cc = p * 64 + c4 * 4;
            dst[(cc + 0) * 33 + k] = v.x;
            dst[(cc + 1) * 33 + k] = v.y;
            dst[(cc + 2) * 33 + k] = v.z;
            dst[(cc + 3) * 33 + k] = v.w;
        }
        __syncthreads();

        u64 a0 = pk2(bb0, bb1), a1 = pk2(bb2, bb3);
        u64 a2 = pk2(bb4, bb5), a3 = pk2(bb6, bb7);
#pragma unroll 8
        for (int cc = 0; cc < 384; cc++) {
            const ulonglong2* wr = (const ulonglong2*)(wsh + cc * 64 + o0);
            const ulonglong2 wv0 = wr[0];
            const ulonglong2 wv1 = wr[1];
            const float xv = xs[cc * 33 + lane];
            const u64 xx = pk2(xv, xv);
            ffma2(a0, xx, wv0.x); ffma2(a1, xx, wv0.y);
            ffma2(a2, xx, wv1.x); ffma2(a3, xx, wv1.y);
        }
        float4 r0, r1;
        unpk(a0, r0.x, r0.y); unpk(a1, r0.z, r0.w);
        unpk(a2, r1.x, r1.y); unpk(a3, r1.z, r1.w);
        const int ob = (pen0 + half) * 512 + lane * 16 + (o0 >> 2);
        out4[ob] = r0; out4[ob + 1] = r1;
        __syncthreads();
    }
}

// ----------------- K5: slice GEMM  slices[i] = a2wt @ W22[i] + terms --------
// grid 768 (i*256 + b*32 + t), 256 threads, 149KB dyn smem.
__global__ void k_slice(const float* __restrict__ W22) {
    extern __shared__ float sm[];
    float* wsh = sm;
    float* ash = sm + 24576;
    const int bid = blockIdx.x;
    const int i = bid >> 8, b = (bid >> 5) & 7, t = bid & 31;
    const int tid = threadIdx.x;
    const int warp = tid >> 5, lane = tid & 31;
    const int o0 = warp * 8;

    float bo[8];
#pragma unroll
    for (int e = 0; e < 8; e++) {
        const int o = o0 + e;
        bo[e] = g_R12[((i * 8 + b) * 32 + t) * 64 + o]
              + g_R12t[((i * 8 + b) * 32 + lane) * 64 + o]
              + g_R02b[(i * 8 + b) * 64 + o];
    }
    u64 acc0 = pk2(bo[0], bo[1]), acc1 = pk2(bo[2], bo[3]);
    u64 acc2 = pk2(bo[4], bo[5]), acc3 = pk2(bo[6], bo[7]);

    const float4* W4 = (const float4*)(W22 + i * 49152);
    const float4* A24 = (const float4*)g_A2;

    for (int tile = 0; tile < 2; tile++) {
        for (int idx = tid; idx < 6144; idx += 256)
            ((float4*)wsh)[idx] = W4[tile * 6144 + idx];
        for (int idx = tid; idx < 3072; idx += 256) {
            const int d = idx / 96, c4 = idx % 96;
            const int P = tile ? d : t, Q = tile ? t : d;
            const float4 v = A24[((b * 32 + P) * 32 + Q) * 96 + c4];
            const int cc = c4 * 4;
            ash[(cc + 0) * 33 + d] = v.x;
            ash[(cc + 1) * 33 + d] = v.y;
            ash[(cc + 2) * 33 + d] = v.z;
            ash[(cc + 3) * 33 + d] = v.w;
        }
        __syncthreads();
#pragma unroll 4
        for (int cc = 0; cc < 384; cc++) {
            const ulonglong2* wr = (const ulonglong2*)(wsh + cc * 64 + o0);
            const ulonglong2 wv0 = wr[0];
            const ulonglong2 wv1 = wr[1];
            const float xv = ash[cc * 33 + lane];
            const u64 xx = pk2(xv, xv);
            ffma2(acc0, xx, wv0.x); ffma2(acc1, xx, wv0.y);
            ffma2(acc2, xx, wv1.x); ffma2(acc3, xx, wv1.y);
        }
        __syncthreads();
    }
    float4 r0, r1;
    unpk(acc0, r0.x, r0.y); unpk(acc1, r0.z, r0.w);
    unpk(acc2, r1.x, r1.y); unpk(acc3, r1.z, r1.w);
    float4* S4 = (float4*)g_S;
    const int ob = (((i * 8 + b) * 32 + t) * 32 + lane) * 16 + (o0 >> 2);
    S4[ob] = r0; S4[ob + 1] = r1;
}

// ----------------- K6: diagonal scatter-add. grid 256, 256 threads ----------
__global__ void k_scatter(float* __restrict__ out) {
    const int bt = blockIdx.x;
    const int b = bt >> 5, t = bt & 31;
    const int tid = threadIdx.x;
    const int dg = tid >> 6, c = tid & 63;
    const float* S0 = g_S + ((0 * 8 + b) * 32 + t) * 2048;
    const float* S1 = g_S + ((1 * 8 + b) * 32 + t) * 2048;
    const float* S2 = g_S + ((2 * 8 + b) * 32 + t) * 2048;
    float* ob = out + b * 2097152;
    for (int d = dg; d < 32; d += 4) {
        const float s0 = S0[d * 64 + c], s1 = S1[d * 64 + c], s2 = S2[d * 64 + c];
        if (d != t) {
            ob[d * 65536 + d * 2048 + t * 64 + c] += s0;   // T[b,d,d,t]
            ob[d * 65536 + t * 2048 + d * 64 + c] += s1;   // T[b,d,t,d]
            ob[t * 65536 + d * 2048 + d * 64 + c] += s2;   // T[b,t,d,d]
        } else {
            ob[d * 65536 + d * 2048 + d * 64 + c] += s0 + s1 + s2 + g_Rmd[(b * 32 + d) * 64 + c];
        }
    }
}

// ---------------------------------------------------------------------------
extern "C" void kernel_launch(void* const* d_in, const int* in_sizes, int n_in,
                              void* d_out, int out_size) {
    const float* x    = (const float*)d_in[0];
    const float* W33  = (const float*)d_in[1];
    const float* b33  = (const float*)d_in[2];
    const float* W22  = (const float*)d_in[3];
    const float* b22  = (const float*)d_in[4];
    const float* W12  = (const float*)d_in[5];
    const float* b12  = (const float*)d_in[6];
    const float* W12t = (const float*)d_in[7];
    const float* b12t = (const float*)d_in[8];
    const float* W02  = (const float*)d_in[9];
    const float* b02  = (const float*)d_in[10];
    const float* W11  = (const float*)d_in[11];
    const float* b11  = (const float*)d_in[12];
    const float* W01  = (const float*)d_in[13];
    const float* b01  = (const float*)d_in[14];
    float* out = (float*)d_out;

    const size_t sm_main  = (24576 + 2 * 384 * 33) * sizeof(float);  // 199680
    const size_t sm_slice = (24576 + 384 * 33) * sizeof(float);      // 148992
    cudaFuncSetAttribute(k_main,  cudaFuncAttributeMaxDynamicSharedMemorySize, (int)sm_main);
    cudaFuncSetAttribute(k_slice, cudaFuncAttributeMaxDynamicSharedMemorySize, (int)sm_slice);

    k_contract<<<dim3(256, 3), 256>>>(x);
    k_a1<<<dim3(8, 10), 256>>>();
    k_a0<<<8, 256>>>();
    k_vec<<<dim3(256, 7), 256>>>(W12, b12, W12t, b12t, W02, b02, W11, b11, W01, b01, b22);
    k_main<<<148, 512, sm_main>>>(x, W33, b33, out);
    k_slice<<<768, 256, sm_slice>>>(W22);
    k_scatter<<<256, 256>>>(out);
}

// round 12
// speedup vs baseline: 1.0265x; 1.0001x over previous
#include <cuda_runtime.h>

typedef unsigned long long u64;

static __device__ __forceinline__ u64 pk2(float lo, float hi) {
    u64 r; asm("mov.b64 %0,{%1,%2};" : "=l"(r) : "f"(lo), "f"(hi)); return r;
}
static __device__ __forceinline__ void unpk(u64 v, float &lo, float &hi) {
    asm("mov.b64 {%0,%1}, %2;" : "=f"(lo), "=f"(hi) : "l"(v));
}
static __device__ __forceinline__ void ffma2(u64 &d, u64 a, u64 b) {
    asm("fma.rn.f32x2 %0, %1, %2, %0;" : "+l"(d) : "l"(a), "l"(b));
}

// ------------------------------ scratch ------------------------------------
__device__ float g_A2[8 * 32 * 32 * 384];      // blocks (s1,s2,s3,d12,d13,d23)
__device__ float g_A1[8 * 32 * 640];           // a1 [B,n,10C]
__device__ float g_A0[8 * 320];                // a0 [B,5C]
__device__ float g_R12 [3 * 8 * 32 * 64];      // a1@W12[i]+b12[i]   (by t)
__device__ float g_R12t[3 * 8 * 32 * 64];      // a1@W12t[i]+b12t[i] (by d)
__device__ float g_R02b[3 * 8 * 64];           // a0@W02[i]+b02[i]+b22[i]
__device__ float g_Rmd [8 * 32 * 64];          // a1@W11+b11 + a0@W01+b01
__device__ float g_S[3 * 8 * 32 * 32 * 64];    // slices [i][b][t][d][64]

// ----------------- K0: s1 contraction, coalesced -----------------------------
// grid 64 (b*8 + jslab), 256 threads. s1[b,j,k,c] = mean_i x[b,i,j,k,c].
// Reads 32KB-contiguous chunks per i-plane (vs 256B strided before).
__global__ void k_s1(const float* __restrict__ x) {
    const int b = blockIdx.x >> 3, js = blockIdx.x & 7;
    const int tid = threadIdx.x;
    const float4* x4 = (const float4*)x;
    float4 acc[8];
#pragma unroll
    for (int r = 0; r < 8; r++) acc[r] = make_float4(0.f, 0.f, 0.f, 0.f);
    for (int i = 0; i < 32; i++) {
        const float4* base = x4 + b * 524288 + i * 16384 + js * 2048;
#pragma unroll
        for (int r = 0; r < 8; r++) {
            const float4 v = base[r * 256 + tid];
            acc[r].x += v.x; acc[r].y += v.y; acc[r].z += v.z; acc[r].w += v.w;
        }
    }
    float4* A24 = (float4*)g_A2;
#pragma unroll
    for (int r = 0; r < 8; r++) {
        const int f = r * 256 + tid;
        const int jj = f >> 9, rem = f & 511, k = rem >> 4, c4 = rem & 15;
        const int j = js * 4 + jj;
        float4 v;
        v.x = acc[r].x * 0.03125f; v.y = acc[r].y * 0.03125f;
        v.z = acc[r].z * 0.03125f; v.w = acc[r].w * 0.03125f;
        A24[((b * 32 + j) * 32 + k) * 96 + c4] = v;   // block 0 (s1)
    }
}

// ----------------- K1: s2+s3 fused pass, diagonals ---------------------------
// grid (256, 2): x = b*32+P.  y=0: s2+s3 single pass; y=1: diags.
__global__ void k_contract(const float* __restrict__ x) {
    const int y = blockIdx.y;
    const int b = blockIdx.x >> 5, P = blockIdx.x & 31;
    const int tid = threadIdx.x;
    const float* xb = x + b * 2097152;
    if (y == 0) {
        __shared__ float ps3[4 * 32 * 64];
        const int c = tid & 63, qs = tid >> 6;
        float s2acc[8] = {0, 0, 0, 0, 0, 0, 0, 0};
        const float* base = xb + P * 65536;
        for (int j = 0; j < 32; j++) {
            float t = 0.f;
#pragma unroll
            for (int kk = 0; kk < 8; kk++) {
                const int k = qs + kk * 4;
                const float v = base[j * 2048 + k * 64 + c];
                s2acc[kk] += v; t += v;
            }
            ps3[(qs * 32 + j) * 64 + c] = t;
        }
        __syncthreads();
#pragma unroll
        for (int kk = 0; kk < 8; kk++) {
            const int k = qs + kk * 4;
            g_A2[((b * 32 + P) * 32 + k) * 384 + 64 + c] = s2acc[kk] * 0.03125f;
        }
        for (int idx = tid; idx < 2048; idx += 256) {
            const int j = idx >> 6, cc = idx & 63;
            const float s = ps3[j * 64 + cc] + ps3[2048 + j * 64 + cc]
                          + ps3[4096 + j * 64 + cc] + ps3[6144 + j * 64 + cc];
            g_A2[((b * 32 + P) * 32 + j) * 384 + 128 + cc] = s * 0.03125f;
        }
    } else {
        for (int idx = tid; idx < 6144; idx += 256) {
            const int kind = idx >> 11;
            const int e = (idx >> 6) & 31, c = idx & 63;
            float v;
            if (kind == 0)      v = xb[e * 65536 + e * 2048 + P * 64 + c];
            else if (kind == 1) v = xb[e * 65536 + P * 2048 + e * 64 + c];
            else                v = xb[P * 65536 + e * 2048 + e * 64 + c];
            g_A2[((b * 32 + P) * 32 + e) * 384 + (3 + kind) * 64 + c] = v;
        }
    }
}

// ----------------- K2: a1 from A2. grid (8, 10), 256 threads ----------------
__global__ void k_a1() {
    const int b = blockIdx.x, blk = blockIdx.y;
    const int tid = threadIdx.x;
    const int t = tid >> 3, c0 = (tid & 7) * 8;
    int off, axis;
    switch (blk) {
        case 0: off = 0;   axis = 0; break;
        case 1: off = 0;   axis = 1; break;
        case 2: off = 64;  axis = 1; break;
        case 3: off = 192; axis = 0; break;
        case 4: off = 192; axis = 1; break;
        case 5: off = 256; axis = 0; break;
        case 6: off = 256; axis = 1; break;
        case 7: off = 320; axis = 0; break;
        case 8: off = 320; axis = 1; break;
        default: off = 320; axis = 2; break;
    }
#pragma unroll
    for (int e = 0; e < 8; e++) {
        const int c = c0 + e;
        float s = 0.f;
        if (axis == 2) {
            s = g_A2[((b * 32 + t) * 32 + t) * 384 + off + c];
        } else if (axis == 0) {
            for (int p = 0; p < 32; p++) s += g_A2[((b * 32 + p) * 32 + t) * 384 + off + c];
            s *= 0.03125f;
        } else {
            for (int q = 0; q < 32; q++) s += g_A2[((b * 32 + t) * 32 + q) * 384 + off + c];
            s *= 0.03125f;
        }
        g_A1[(b * 32 + t) * 640 + blk * 64 + c] = s;
    }
}

// ----------------- K2b: a0 from a1. grid 8, 256 threads ---------------------
__global__ void k_a0() {
    const int b = blockIdx.x;
    const int srcmap[5] = {2, 4, 6, 8, 9};
    for (int idx = threadIdx.x; idx < 320; idx += 256) {
        const int blk = idx >> 6, c = idx & 63;
        const int so = srcmap[blk] * 64 + c;
        float s = 0.f;
        for (int t = 0; t < 32; t++) s += g_A1[(b * 32 + t) * 640 + so];
        g_A0[b * 320 + idx] = s * 0.03125f;
    }
}

// ----------------- K4: vector mixes. grid (256, 7), 256 threads -------------
__global__ void k_vec(const float* __restrict__ W12, const float* __restrict__ b12,
                      const float* __restrict__ W12t, const float* __restrict__ b12t,
                      const float* __restrict__ W02, const float* __restrict__ b02,
                      const float* __restrict__ W11, const float* __restrict__ b11,
                      const float* __restrict__ W01, const float* __restrict__ b01,
                      const float* __restrict__ b22) {
    __shared__ float a1sh[640];
    __shared__ float a0sh[320];
    __shared__ float psum[4][64];
    __shared__ float psum2[4][64];
    const int row = blockIdx.x;            // b*32 + t
    const int y = blockIdx.y;
    const int tid = threadIdx.x;
    const int o = tid & 63, chunk = tid >> 6;
    const int b = row >> 5, t = row & 31;

    for (int idx = tid; idx < 640; idx += 256) a1sh[idx] = g_A1[row * 640 + idx];
    if (y == 6) for (int idx = tid; idx < 320; idx += 256) a0sh[idx] = g_A0[b * 320 + idx];
    __syncthreads();

    const float* W; float* dst;
    if (y < 3)      { W = W12  + y * 40960;        dst = g_R12  + (y * 256 + row) * 64; }
    else if (y < 6) { W = W12t + (y - 3) * 40960;  dst = g_R12t + ((y - 3) * 256 + row) * 64; }
    else            { W = W11;                     dst = g_Rmd + row * 64; }

    float acc = 0.f;
    const int k0 = chunk * 160;
#pragma unroll 8
    for (int k = k0; k < k0 + 160; k++)
        acc += a1sh[k] * __ldg(W + k * 64 + o);
    if (y == 6) {
#pragma unroll 8
        for (int k = chunk * 80; k < chunk * 80 + 80; k++)
            acc += a0sh[k] * __ldg(W01 + k * 64 + o);
    }
    psum[chunk][o] = acc;

    if (y == 6 && t < 3) {
        float acc2 = 0.f;
#pragma unroll 8
        for (int k = chunk * 80; k < chunk * 80 + 80; k++)
            acc2 += a0sh[k] * __ldg(W02 + t * 20480 + k * 64 + o);
        psum2[chunk][o] = acc2;
    }
    __syncthreads();
    if (chunk == 0) {
        float s = psum[0][o] + psum[1][o] + psum[2][o] + psum[3][o];
        if (y < 3)      s += __ldg(b12  + y * 64 + o);
        else if (y < 6) s += __ldg(b12t + (y - 3) * 64 + o);
        else            s += __ldg(b11 + o) + __ldg(b01 + o);
        dst[o] = s;
        if (y == 6 && t < 3) {
            float s2 = psum2[0][o] + psum2[1][o] + psum2[2][o] + psum2[3][o]
                     + __ldg(b02 + t * 64 + o) + __ldg(b22 + t * 64 + o);
            g_R02b[(t * 8 + b) * 64 + o] = s2;
        }
    }
}

// ----------------- K3: main GEMM  T = allp @ W33 + b33 ----------------------
// Symmetry pairing: output pencils (i,j) and (j,i) share the SAME 6 gathered
// pencils (buffer permutation [2,4,0,5,1,3]). One staged set serves both.
// grid 148 persistent, 512 threads: warps 0-7 -> (i,j), warps 8-15 -> (j,i).
// smem: wsh[384*64] + xsh[384*33] = 149KB.
__global__ void k_main(const float* __restrict__ x, const float* __restrict__ W33,
                       const float* __restrict__ b33, float* __restrict__ out) {
    extern __shared__ float sm[];
    float* wsh = sm;            // 24576 floats
    float* xsh = sm + 24576;    // 12672 floats
    const int tid = threadIdx.x;
    const int warp = tid >> 5, lane = tid & 31;
    const int half = warp >> 3;
    const int o0 = (warp & 7) * 8;

    const float4* W4 = (const float4*)W33;
    float4* wsh4 = (float4*)wsh;
    for (int idx = tid; idx < 6144; idx += 512) wsh4[idx] = W4[idx];

    const float4* x4 = (const float4*)x;
    float4* out4 = (float4*)out;

    const float bb0 = __ldg(b33 + o0 + 0), bb1 = __ldg(b33 + o0 + 1);
    const float bb2 = __ldg(b33 + o0 + 2), bb3 = __ldg(b33 + o0 + 3);
    const float bb4 = __ldg(b33 + o0 + 4), bb5 = __ldg(b33 + o0 + 5);
    const float bb6 = __ldg(b33 + o0 + 6), bb7 = __ldg(b33 + o0 + 7);

    __syncthreads();

    // units: per b, 528 (i<=j) pairs. total 4224.
    for (int unit = blockIdx.x; unit < 4224; unit += gridDim.x) {
        const int b = unit / 528;
        int rr = unit - b * 528;
        int i = 0;
        while (rr >= 32 - i) { rr -= 32 - i; i++; }
        const int j = i + rr;

        // stage the 6 permutation pencils for (i,j): xsh[cc][k], cc = p*64+c
        for (int idx = tid; idx < 3072; idx += 512) {
            const int p = idx >> 9, rem = idx & 511, k = rem >> 4, c4 = rem & 15;
            int A, B, C;
            switch (p) {
                case 0: A = i; B = j; C = k; break;   // x[b,i,j,k]
                case 1: A = i; B = k; C = j; break;   // x[b,i,k,j]
                case 2: A = j; B = i; C = k; break;   // x[b,j,i,k]
                case 3: A = k; B = i; C = j; break;   // x[b,k,i,j]
                case 4: A = j; B = k; C = i; break;   // x[b,j,k,i]
                default: A = k; B = j; C = i; break;  // x[b,k,j,i]
            }
            const float4 v = x4[b * 524288 + A * 16384 + B * 512 + C * 16 + c4];
            const int cc = p * 64 + c4 * 4;
            xsh[(cc + 0) * 33 + k] = v.x;
            xsh[(cc + 1) * 33 + k] = v.y;
            xsh[(cc + 2) * 33 + k] = v.z;
            xsh[(cc + 3) * 33 + k] = v.w;
        }
        __syncthreads();

        u64 a0 = pk2(bb0, bb1), a1 = pk2(bb2, bb3);
        u64 a2 = pk2(bb4, bb5), a3 = pk2(bb6, bb7);
        const int map1[6] = {2, 4, 0, 5, 1, 3};   // buffer order for (j,i)
#pragma unroll
        for (int p = 0; p < 6; p++) {
            const int bp = half ? map1[p] : p;
            const float* xb = xsh + bp * 2112;            // 64*33
            const float* wp = wsh + (p << 6) * 64 + o0;
#pragma unroll 8
            for (int c = 0; c < 64; c++) {
                const ulonglong2* wr = (const ulonglong2*)(wp + c * 64);
                const ulonglong2 wv0 = wr[0];
                const ulonglong2 wv1 = wr[1];
                const float xv = xb[c * 33 + lane];
                const u64 xx = pk2(xv, xv);
                ffma2(a0, xx, wv0.x); ffma2(a1, xx, wv0.y);
                ffma2(a2, xx, wv1.x); ffma2(a3, xx, wv1.y);
            }
        }
        if (half == 0 || i != j) {
            const int I = half ? j : i, J = half ? i : j;
            float4 r0, r1;
            unpk(a0, r0.x, r0.y); unpk(a1, r0.z, r0.w);
            unpk(a2, r1.x, r1.y); unpk(a3, r1.z, r1.w);
            const int pen = (b * 32 + I) * 32 + J;
            const int ob = pen * 512 + lane * 16 + (o0 >> 2);
            out4[ob] = r0; out4[ob + 1] = r1;
        }
        __syncthreads();
    }
}

// ----------------- K5: slice GEMM  slices[i] = a2wt @ W22[i] + terms --------
// grid 768 (i*256 + b*32 + t), 256 threads, 149KB dyn smem.
__global__ void k_slice(const float* __restrict__ W22) {
    extern __shared__ float sm[];
    float* wsh = sm;
    float* ash = sm + 24576;
    const int bid = blockIdx.x;
    const int i = bid >> 8, b = (bid >> 5) & 7, t = bid & 31;
    const int tid = threadIdx.x;
    const int warp = tid >> 5, lane = tid & 31;
    const int o0 = warp * 8;

    float bo[8];
#pragma unroll
    for (int e = 0; e < 8; e++) {
        const int o = o0 + e;
        bo[e] = g_R12[((i * 8 + b) * 32 + t) * 64 + o]
              + g_R12t[((i * 8 + b) * 32 + lane) * 64 + o]
              + g_R02b[(i * 8 + b) * 64 + o];
    }
    u64 acc0 = pk2(bo[0], bo[1]), acc1 = pk2(bo[2], bo[3]);
    u64 acc2 = pk2(bo[4], bo[5]), acc3 = pk2(bo[6], bo[7]);

    const float4* W4 = (const float4*)(W22 + i * 49152);
    const float4* A24 = (const float4*)g_A2;

    for (int tile = 0; tile < 2; tile++) {
        for (int idx = tid; idx < 6144; idx += 256)
            ((float4*)wsh)[idx] = W4[tile * 6144 + idx];
        for (int idx = tid; idx < 3072; idx += 256) {
            const int d = idx / 96, c4 = idx % 96;
            const int P = tile ? d : t, Q = tile ? t : d;
            const float4 v = A24[((b * 32 + P) * 32 + Q) * 96 + c4];
            const int cc = c4 * 4;
            ash[(cc + 0) * 33 + d] = v.x;
            ash[(cc + 1) * 33 + d] = v.y;
            ash[(cc + 2) * 33 + d] = v.z;
            ash[(cc + 3) * 33 + d] = v.w;
        }
        __syncthreads();
#pragma unroll 4
        for (int cc = 0; cc < 384; cc++) {
            const ulonglong2* wr = (const ulonglong2*)(wsh + cc * 64 + o0);
            const ulonglong2 wv0 = wr[0];
            const ulonglong2 wv1 = wr[1];
            const float xv = ash[cc * 33 + lane];
            const u64 xx = pk2(xv, xv);
            ffma2(acc0, xx, wv0.x); ffma2(acc1, xx, wv0.y);
            ffma2(acc2, xx, wv1.x); ffma2(acc3, xx, wv1.y);
        }
        __syncthreads();
    }
    float4 r0, r1;
    unpk(acc0, r0.x, r0.y); unpk(acc1, r0.z, r0.w);
    unpk(acc2, r1.x, r1.y); unpk(acc3, r1.z, r1.w);
    float4* S4 = (float4*)g_S;
    const int ob = (((i * 8 + b) * 32 + t) * 32 + lane) * 16 + (o0 >> 2);
    S4[ob] = r0; S4[ob + 1] = r1;
}

// ----------------- K6: diagonal scatter-add. grid 256, 256 threads ----------
__global__ void k_scatter(float* __restrict__ out) {
    const int bt = blockIdx.x;
    const int b = bt >> 5, t = bt & 31;
    const int tid = threadIdx.x;
    const int dg = tid >> 6, c = tid & 63;
    const float* S0 = g_S + ((0 * 8 + b) * 32 + t) * 2048;
    const float* S1 = g_S + ((1 * 8 + b) * 32 + t) * 2048;
    const float* S2 = g_S + ((2 * 8 + b) * 32 + t) * 2048;
    float* ob = out + b * 2097152;
    for (int d = dg; d < 32; d += 4) {
        const float s0 = S0[d * 64 + c], s1 = S1[d * 64 + c], s2 = S2[d * 64 + c];
        if (d != t) {
            ob[d * 65536 + d * 2048 + t * 64 + c] += s0;   // T[b,d,d,t]
            ob[d * 65536 + t * 2048 + d * 64 + c] += s1;   // T[b,d,t,d]
            ob[t * 65536 + d * 2048 + d * 64 + c] += s2;   // T[b,t,d,d]
        } else {
            ob[d * 65536 + d * 2048 + d * 64 + c] += s0 + s1 + s2 + g_Rmd[(b * 32 + d) * 64 + c];
        }
    }
}

// ---------------------------------------------------------------------------
extern "C" void kernel_launch(void* const* d_in, const int* in_sizes, int n_in,
                              void* d_out, int out_size) {
    const float* x    = (const float*)d_in[0];
    const float* W33  = (const float*)d_in[1];
    const float* b33  = (const float*)d_in[2];
    const float* W22  = (const float*)d_in[3];
    const float* b22  = (const float*)d_in[4];
    const float* W12  = (const float*)d_in[5];
    const float* b12  = (const float*)d_in[6];
    const float* W12t = (const float*)d_in[7];
    const float* b12t = (const float*)d_in[8];
    const float* W02  = (const float*)d_in[9];
    const float* b02  = (const float*)d_in[10];
    const float* W11  = (const float*)d_in[11];
    const float* b11  = (const float*)d_in[12];
    const float* W01  = (const float*)d_in[13];
    const float* b01  = (const float*)d_in[14];
    float* out = (float*)d_out;

    const size_t sm_gemm = (24576 + 384 * 33) * sizeof(float);  // 148992
    cudaFuncSetAttribute(k_main,  cudaFuncAttributeMaxDynamicSharedMemorySize, (int)sm_gemm);
    cudaFuncSetAttribute(k_slice, cudaFuncAttributeMaxDynamicSharedMemorySize, (int)sm_gemm);

    // launch index 3 = k_main -> ncu capture target
    k_s1<<<64, 256>>>(x);
    k_contract<<<dim3(256, 2), 256>>>(x);
    k_a1<<<dim3(8, 10), 256>>>();
    k_main<<<148, 512, sm_gemm>>>(x, W33, b33, out);
    k_a0<<<8, 256>>>();
    k_vec<<<dim3(256, 7), 256>>>(W12, b12, W12t, b12t, W02, b02, W11, b11, W01, b01, b22);
    k_slice<<<768, 256, sm_gemm>>>(W22);
    k_scatter<<<256, 256>>>(out);
}

// round 13
// speedup vs baseline: 1.1677x; 1.1376x over previous
#include <cuda_runtime.h>

typedef unsigned long long u64;

static __device__ __forceinline__ u64 pk2(float lo, float hi) {
    u64 r; asm("mov.b64 %0,{%1,%2};" : "=l"(r) : "f"(lo), "f"(hi)); return r;
}
static __device__ __forceinline__ void unpk(u64 v, float &lo, float &hi) {
    asm("mov.b64 {%0,%1}, %2;" : "=f"(lo), "=f"(hi) : "l"(v));
}
static __device__ __forceinline__ void ffma2(u64 &d, u64 a, u64 b) {
    asm("fma.rn.f32x2 %0, %1, %2, %0;" : "+l"(d) : "l"(a), "l"(b));
}

// ------------------------------ scratch ------------------------------------
__device__ float g_A2[8 * 32 * 32 * 384];      // blocks (s1,s2,s3,d12,d13,d23)
__device__ float g_A1[8 * 32 * 640];           // a1 [B,n,10C]
__device__ float g_A0[8 * 320];                // a0 [B,5C]
__device__ float g_R12 [3 * 8 * 32 * 64];      // a1@W12[i]+b12[i]   (by t)
__device__ float g_R12t[3 * 8 * 32 * 64];      // a1@W12t[i]+b12t[i] (by d)
__device__ float g_R02b[3 * 8 * 64];           // a0@W02[i]+b02[i]+b22[i]
__device__ float g_Rmd [8 * 32 * 64];          // a1@W11+b11 + a0@W01+b01
__device__ float g_S[3 * 8 * 32 * 32 * 64];    // slices [i][b][t][d][64]

// ----------------- K0: s1 contraction, coalesced -----------------------------
__global__ void k_s1(const float* __restrict__ x) {
    const int b = blockIdx.x >> 3, js = blockIdx.x & 7;
    const int tid = threadIdx.x;
    const float4* x4 = (const float4*)x;
    float4 acc[8];
#pragma unroll
    for (int r = 0; r < 8; r++) acc[r] = make_float4(0.f, 0.f, 0.f, 0.f);
    for (int i = 0; i < 32; i++) {
        const float4* base = x4 + b * 524288 + i * 16384 + js * 2048;
#pragma unroll
        for (int r = 0; r < 8; r++) {
            const float4 v = base[r * 256 + tid];
            acc[r].x += v.x; acc[r].y += v.y; acc[r].z += v.z; acc[r].w += v.w;
        }
    }
    float4* A24 = (float4*)g_A2;
#pragma unroll
    for (int r = 0; r < 8; r++) {
        const int f = r * 256 + tid;
        const int jj = f >> 9, rem = f & 511, k = rem >> 4, c4 = rem & 15;
        const int j = js * 4 + jj;
        float4 v;
        v.x = acc[r].x * 0.03125f; v.y = acc[r].y * 0.03125f;
        v.z = acc[r].z * 0.03125f; v.w = acc[r].w * 0.03125f;
        A24[((b * 32 + j) * 32 + k) * 96 + c4] = v;
    }
}

// ----------------- K1: s2+s3 fused pass, diagonals ---------------------------
__global__ void k_contract(const float* __restrict__ x) {
    const int y = blockIdx.y;
    const int b = blockIdx.x >> 5, P = blockIdx.x & 31;
    const int tid = threadIdx.x;
    const float* xb = x + b * 2097152;
    if (y == 0) {
        __shared__ float ps3[4 * 32 * 64];
        const int c = tid & 63, qs = tid >> 6;
        float s2acc[8] = {0, 0, 0, 0, 0, 0, 0, 0};
        const float* base = xb + P * 65536;
        for (int j = 0; j < 32; j++) {
            float t = 0.f;
#pragma unroll
            for (int kk = 0; kk < 8; kk++) {
                const int k = qs + kk * 4;
                const float v = base[j * 2048 + k * 64 + c];
                s2acc[kk] += v; t += v;
            }
            ps3[(qs * 32 + j) * 64 + c] = t;
        }
        __syncthreads();
#pragma unroll
        for (int kk = 0; kk < 8; kk++) {
            const int k = qs + kk * 4;
            g_A2[((b * 32 + P) * 32 + k) * 384 + 64 + c] = s2acc[kk] * 0.03125f;
        }
        for (int idx = tid; idx < 2048; idx += 256) {
            const int j = idx >> 6, cc = idx & 63;
            const float s = ps3[j * 64 + cc] + ps3[2048 + j * 64 + cc]
                          + ps3[4096 + j * 64 + cc] + ps3[6144 + j * 64 + cc];
            g_A2[((b * 32 + P) * 32 + j) * 384 + 128 + cc] = s * 0.03125f;
        }
    } else {
        for (int idx = tid; idx < 6144; idx += 256) {
            const int kind = idx >> 11;
            const int e = (idx >> 6) & 31, c = idx & 63;
            float v;
            if (kind == 0)      v = xb[e * 65536 + e * 2048 + P * 64 + c];
            else if (kind == 1) v = xb[e * 65536 + P * 2048 + e * 64 + c];
            else                v = xb[P * 65536 + e * 2048 + e * 64 + c];
            g_A2[((b * 32 + P) * 32 + e) * 384 + (3 + kind) * 64 + c] = v;
        }
    }
}

// ----------------- K2: a1 from A2. grid (8, 10), 256 threads ----------------
__global__ void k_a1() {
    const int b = blockIdx.x, blk = blockIdx.y;
    const int tid = threadIdx.x;
    const int t = tid >> 3, c0 = (tid & 7) * 8;
    int off, axis;
    switch (blk) {
        case 0: off = 0;   axis = 0; break;
        case 1: off = 0;   axis = 1; break;
        case 2: off = 64;  axis = 1; break;
        case 3: off = 192; axis = 0; break;
        case 4: off = 192; axis = 1; break;
        case 5: off = 256; axis = 0; break;
        case 6: off = 256; axis = 1; break;
        case 7: off = 320; axis = 0; break;
        case 8: off = 320; axis = 1; break;
        default: off = 320; axis = 2; break;
    }
#pragma unroll
    for (int e = 0; e < 8; e++) {
        const int c = c0 + e;
        float s = 0.f;
        if (axis == 2) {
            s = g_A2[((b * 32 + t) * 32 + t) * 384 + off + c];
        } else if (axis == 0) {
            for (int p = 0; p < 32; p++) s += g_A2[((b * 32 + p) * 32 + t) * 384 + off + c];
            s *= 0.03125f;
        } else {
            for (int q = 0; q < 32; q++) s += g_A2[((b * 32 + t) * 32 + q) * 384 + off + c];
            s *= 0.03125f;
        }
        g_A1[(b * 32 + t) * 640 + blk * 64 + c] = s;
    }
}

// ----------------- K2b: a0 from a1. grid 8, 256 threads ---------------------
__global__ void k_a0() {
    const int b = blockIdx.x;
    const int srcmap[5] = {2, 4, 6, 8, 9};
    for (int idx = threadIdx.x; idx < 320; idx += 256) {
        const int blk = idx >> 6, c = idx & 63;
        const int so = srcmap[blk] * 64 + c;
        float s = 0.f;
        for (int t = 0; t < 32; t++) s += g_A1[(b * 32 + t) * 640 + so];
        g_A0[b * 320 + idx] = s * 0.03125f;
    }
}

// ----------------- K4: vector mixes. grid (256, 7), 256 threads -------------
__global__ void k_vec(const float* __restrict__ W12, const float* __restrict__ b12,
                      const float* __restrict__ W12t, const float* __restrict__ b12t,
                      const float* __restrict__ W02, const float* __restrict__ b02,
                      const float* __restrict__ W11, const float* __restrict__ b11,
                      const float* __restrict__ W01, const float* __restrict__ b01,
                      const float* __restrict__ b22) {
    __shared__ float a1sh[640];
    __shared__ float a0sh[320];
    __shared__ float psum[4][64];
    __shared__ float psum2[4][64];
    const int row = blockIdx.x;            // b*32 + t
    const int y = blockIdx.y;
    const int tid = threadIdx.x;
    const int o = tid & 63, chunk = tid >> 6;
    const int b = row >> 5, t = row & 31;

    for (int idx = tid; idx < 640; idx += 256) a1sh[idx] = g_A1[row * 640 + idx];
    if (y == 6) for (int idx = tid; idx < 320; idx += 256) a0sh[idx] = g_A0[b * 320 + idx];
    __syncthreads();

    const float* W; float* dst;
    if (y < 3)      { W = W12  + y * 40960;        dst = g_R12  + (y * 256 + row) * 64; }
    else if (y < 6) { W = W12t + (y - 3) * 40960;  dst = g_R12t + ((y - 3) * 256 + row) * 64; }
    else            { W = W11;                     dst = g_Rmd + row * 64; }

    float acc = 0.f;
    const int k0 = chunk * 160;
#pragma unroll 8
    for (int k = k0; k < k0 + 160; k++)
        acc += a1sh[k] * __ldg(W + k * 64 + o);
    if (y == 6) {
#pragma unroll 8
        for (int k = chunk * 80; k < chunk * 80 + 80; k++)
            acc += a0sh[k] * __ldg(W01 + k * 64 + o);
    }
    psum[chunk][o] = acc;

    if (y == 6 && t < 3) {
        float acc2 = 0.f;
#pragma unroll 8
        for (int k = chunk * 80; k < chunk * 80 + 80; k++)
            acc2 += a0sh[k] * __ldg(W02 + t * 20480 + k * 64 + o);
        psum2[chunk][o] = acc2;
    }
    __syncthreads();
    if (chunk == 0) {
        float s = psum[0][o] + psum[1][o] + psum[2][o] + psum[3][o];
        if (y < 3)      s += __ldg(b12  + y * 64 + o);
        else if (y < 6) s += __ldg(b12t + (y - 3) * 64 + o);
        else            s += __ldg(b11 + o) + __ldg(b01 + o);
        dst[o] = s;
        if (y == 6 && t < 3) {
            float s2 = psum2[0][o] + psum2[1][o] + psum2[2][o] + psum2[3][o]
                     + __ldg(b02 + t * 64 + o) + __ldg(b22 + t * 64 + o);
            g_R02b[(t * 8 + b) * 64 + o] = s2;
        }
    }
}

// ----------------- K3: main GEMM  T = allp @ W33 + b33 ----------------------
// Stage TWO symmetry units (4 pencils) per iteration; each warp computes its
// 8 channels for ALL 4 pencils -> W broadcast amortized 4x.
// grid 148 persistent, 256 threads. smem: wsh[384*64] + 2 x xsh[384*33] = 199.7KB.
__global__ void k_main(const float* __restrict__ x, const float* __restrict__ W33,
                       const float* __restrict__ b33, float* __restrict__ out) {
    extern __shared__ float sm[];
    float* wsh  = sm;                   // 24576
    float* xshA = sm + 24576;           // unit0: 12672
    float* xshB = sm + 24576 + 12672;   // unit1: 12672
    const int tid = threadIdx.x;
    const int warp = tid >> 5, lane = tid & 31;
    const int o0 = warp * 8;

    const float4* W4 = (const float4*)W33;
    float4* wsh4 = (float4*)wsh;
    for (int idx = tid; idx < 6144; idx += 256) wsh4[idx] = W4[idx];

    const float4* x4 = (const float4*)x;
    float4* out4 = (float4*)out;

    const u64 bi0 = pk2(__ldg(b33 + o0 + 0), __ldg(b33 + o0 + 1));
    const u64 bi1 = pk2(__ldg(b33 + o0 + 2), __ldg(b33 + o0 + 3));
    const u64 bi2 = pk2(__ldg(b33 + o0 + 4), __ldg(b33 + o0 + 5));
    const u64 bi3 = pk2(__ldg(b33 + o0 + 6), __ldg(b33 + o0 + 7));

    __syncthreads();

    // 4224 units (b, i<=j); paired 2 per iteration -> 2112 pair-iters.
    for (int pr = blockIdx.x; pr < 2112; pr += gridDim.x) {
        const int u0 = pr * 2, u1 = pr * 2 + 1;
        const int b0 = u0 / 528; int r0 = u0 - b0 * 528;
        int i0 = 0; while (r0 >= 32 - i0) { r0 -= 32 - i0; i0++; }
        const int j0 = i0 + r0;
        const int b1 = u1 / 528; int r1 = u1 - b1 * 528;
        int i1 = 0; while (r1 >= 32 - i1) { r1 -= 32 - i1; i1++; }
        const int j1 = i1 + r1;

        // stage 6 permutation pencils for both units
        for (int idx = tid; idx < 6144; idx += 256) {
            const int h = idx / 3072;
            const int id2 = idx - h * 3072;
            const int p = id2 >> 9, rem = id2 & 511, k = rem >> 4, c4 = rem & 15;
            const int bb = h ? b1 : b0, i = h ? i1 : i0, j = h ? j1 : j0;
            int A, B, C;
            switch (p) {
                case 0: A = i; B = j; C = k; break;
                case 1: A = i; B = k; C = j; break;
                case 2: A = j; B = i; C = k; break;
                case 3: A = k; B = i; C = j; break;
                case 4: A = j; B = k; C = i; break;
                default: A = k; B = j; C = i; break;
            }
            const float4 v = x4[bb * 524288 + A * 16384 + B * 512 + C * 16 + c4];
            float* dst = h ? xshB : xshA;
            const int cc = p * 64 + c4 * 4;
            dst[(cc + 0) * 33 + k] = v.x;
            dst[(cc + 1) * 33 + k] = v.y;
            dst[(cc + 2) * 33 + k] = v.z;
            dst[(cc + 3) * 33 + k] = v.w;
        }
        __syncthreads();

        // 4 pencils: A=(i0,j0) B=(j0,i0) C=(i1,j1) D=(j1,i1)
        u64 aA0 = bi0, aA1 = bi1, aA2 = bi2, aA3 = bi3;
        u64 aB0 = bi0, aB1 = bi1, aB2 = bi2, aB3 = bi3;
        u64 aC0 = bi0, aC1 = bi1, aC2 = bi2, aC3 = bi3;
        u64 aD0 = bi0, aD1 = bi1, aD2 = bi2, aD3 = bi3;
        const int map1[6] = {2, 4, 0, 5, 1, 3};   // buffer order for transposed pencil
#pragma unroll
        for (int p = 0; p < 6; p++) {
            const float* xA = xshA + p * 2112;
            const float* xB = xshA + map1[p] * 2112;
            const float* xC = xshB + p * 2112;
            const float* xD = xshB + map1[p] * 2112;
            const float* wp = wsh + (p << 12) + o0;   // p*64*64
#pragma unroll 8
            for (int c = 0; c < 64; c++) {
                const ulonglong2* wr = (const ulonglong2*)(wp + c * 64);
                const ulonglong2 wv0 = wr[0];
                const ulonglong2 wv1 = wr[1];
                const int xo = c * 33 + lane;
                const u64 va = pk2(xA[xo], xA[xo]);
                const u64 vb = pk2(xB[xo], xB[xo]);
                const u64 vc = pk2(xC[xo], xC[xo]);
                const u64 vd = pk2(xD[xo], xD[xo]);
                ffma2(aA0, va, wv0.x); ffma2(aA1, va, wv0.y);
                ffma2(aA2, va, wv1.x); ffma2(aA3, va, wv1.y);
                ffma2(aB0, vb, wv0.x); ffma2(aB1, vb, wv0.y);
                ffma2(aB2, vb, wv1.x); ffma2(aB3, vb, wv1.y);
                ffma2(aC0, vc, wv0.x); ffma2(aC1, vc, wv0.y);
                ffma2(aC2, vc, wv1.x); ffma2(aC3, vc, wv1.y);
                ffma2(aD0, vd, wv0.x); ffma2(aD1, vd, wv0.y);
                ffma2(aD2, vd, wv1.x); ffma2(aD3, vd, wv1.y);
            }
        }
        float4 r0v, r1v;
        // pencil A: (b0, i0, j0)
        unpk(aA0, r0v.x, r0v.y); unpk(aA1, r0v.z, r0v.w);
        unpk(aA2, r1v.x, r1v.y); unpk(aA3, r1v.z, r1v.w);
        int ob = ((b0 * 32 + i0) * 32 + j0) * 512 + lane * 16 + (o0 >> 2);
        out4[ob] = r0v; out4[ob + 1] = r1v;
        // pencil B: (b0, j0, i0) if distinct
        if (i0 != j0) {
            unpk(aB0, r0v.x, r0v.y); unpk(aB1, r0v.z, r0v.w);
            unpk(aB2, r1v.x, r1v.y); unpk(aB3, r1v.z, r1v.w);
            ob = ((b0 * 32 + j0) * 32 + i0) * 512 + lane * 16 + (o0 >> 2);
            out4[ob] = r0v; out4[ob + 1] = r1v;
        }
        // pencil C: (b1, i1, j1)
        unpk(aC0, r0v.x, r0v.y); unpk(aC1, r0v.z, r0v.w);
        unpk(aC2, r1v.x, r1v.y); unpk(aC3, r1v.z, r1v.w);
        ob = ((b1 * 32 + i1) * 32 + j1) * 512 + lane * 16 + (o0 >> 2);
        out4[ob] = r0v; out4[ob + 1] = r1v;
        // pencil D: (b1, j1, i1) if distinct
        if (i1 != j1) {
            unpk(aD0, r0v.x, r0v.y); unpk(aD1, r0v.z, r0v.w);
            unpk(aD2, r1v.x, r1v.y); unpk(aD3, r1v.z, r1v.w);
            ob = ((b1 * 32 + j1) * 32 + i1) * 512 + lane * 16 + (o0 >> 2);
            out4[ob] = r0v; out4[ob + 1] = r1v;
        }
        __syncthreads();
    }
}

// ----------------- K5: slice GEMM  slices[i] = a2wt @ W22[i] + terms --------
__global__ void k_slice(const float* __restrict__ W22) {
    extern __shared__ float sm[];
    float* wsh = sm;
    float* ash = sm + 24576;
    const int bid = blockIdx.x;
    const int i = bid >> 8, b = (bid >> 5) & 7, t = bid & 31;
    const int tid = threadIdx.x;
    const int warp = tid >> 5, lane = tid & 31;
    const int o0 = warp * 8;

    float bo[8];
#pragma unroll
    for (int e = 0; e < 8; e++) {
        const int o = o0 + e;
        bo[e] = g_R12[((i * 8 + b) * 32 + t) * 64 + o]
              + g_R12t[((i * 8 + b) * 32 + lane) * 64 + o]
              + g_R02b[(i * 8 + b) * 64 + o];
    }
    u64 acc0 = pk2(bo[0], bo[1]), acc1 = pk2(bo[2], bo[3]);
    u64 acc2 = pk2(bo[4], bo[5]), acc3 = pk2(bo[6], bo[7]);

    const float4* W4 = (const float4*)(W22 + i * 49152);
    const float4* A24 = (const float4*)g_A2;

    for (int tile = 0; tile < 2; tile++) {
        for (int idx = tid; idx < 6144; idx += 256)
            ((float4*)wsh)[idx] = W4[tile * 6144 + idx];
        for (int idx = tid; idx < 3072; idx += 256) {
            const int d = idx / 96, c4 = idx % 96;
            const int P = tile ? d : t, Q = tile ? t : d;
            const float4 v = A24[((b * 32 + P) * 32 + Q) * 96 + c4];
            const int cc = c4 * 4;
            ash[(cc + 0) * 33 + d] = v.x;
            ash[(cc + 1) * 33 + d] = v.y;
            ash[(cc + 2) * 33 + d] = v.z;
            ash[(cc + 3) * 33 + d] = v.w;
        }
        __syncthreads();
#pragma unroll 4
        for (int cc = 0; cc < 384; cc++) {
            const ulonglong2* wr = (const ulonglong2*)(wsh + cc * 64 + o0);
            const ulonglong2 wv0 = wr[0];
            const ulonglong2 wv1 = wr[1];
            const float xv = ash[cc * 33 + lane];
            const u64 xx = pk2(xv, xv);
            ffma2(acc0, xx, wv0.x); ffma2(acc1, xx, wv0.y);
            ffma2(acc2, xx, wv1.x); ffma2(acc3, xx, wv1.y);
        }
        __syncthreads();
    }
    float4 r0, r1;
    unpk(acc0, r0.x, r0.y); unpk(acc1, r0.z, r0.w);
    unpk(acc2, r1.x, r1.y); unpk(acc3, r1.z, r1.w);
    float4* S4 = (float4*)g_S;
    const int ob = (((i * 8 + b) * 32 + t) * 32 + lane) * 16 + (o0 >> 2);
    S4[ob] = r0; S4[ob + 1] = r1;
}

// ----------------- K6: diagonal scatter-add. grid 256, 256 threads ----------
__global__ void k_scatter(float* __restrict__ out) {
    const int bt = blockIdx.x;
    const int b = bt >> 5, t = bt & 31;
    const int tid = threadIdx.x;
    const int dg = tid >> 6, c = tid & 63;
    const float* S0 = g_S + ((0 * 8 + b) * 32 + t) * 2048;
    const float* S1 = g_S + ((1 * 8 + b) * 32 + t) * 2048;
    const float* S2 = g_S + ((2 * 8 + b) * 32 + t) * 2048;
    float* ob = out + b * 2097152;
    for (int d = dg; d < 32; d += 4) {
        const float s0 = S0[d * 64 + c], s1 = S1[d * 64 + c], s2 = S2[d * 64 + c];
        if (d != t) {
            ob[d * 65536 + d * 2048 + t * 64 + c] += s0;   // T[b,d,d,t]
            ob[d * 65536 + t * 2048 + d * 64 + c] += s1;   // T[b,d,t,d]
            ob[t * 65536 + d * 2048 + d * 64 + c] += s2;   // T[b,t,d,d]
        } else {
            ob[d * 65536 + d * 2048 + d * 64 + c] += s0 + s1 + s2 + g_Rmd[(b * 32 + d) * 64 + c];
        }
    }
}

// ---------------------------------------------------------------------------
extern "C" void kernel_launch(void* const* d_in, const int* in_sizes, int n_in,
                              void* d_out, int out_size) {
    const float* x    = (const float*)d_in[0];
    const float* W33  = (const float*)d_in[1];
    const float* b33  = (const float*)d_in[2];
    const float* W22  = (const float*)d_in[3];
    const float* b22  = (const float*)d_in[4];
    const float* W12  = (const float*)d_in[5];
    const float* b12  = (const float*)d_in[6];
    const float* W12t = (const float*)d_in[7];
    const float* b12t = (const float*)d_in[8];
    const float* W02  = (const float*)d_in[9];
    const float* b02  = (const float*)d_in[10];
    const float* W11  = (const float*)d_in[11];
    const float* b11  = (const float*)d_in[12];
    const float* W01  = (const float*)d_in[13];
    const float* b01  = (const float*)d_in[14];
    float* out = (float*)d_out;

    const size_t sm_main  = (24576 + 2 * 384 * 33) * sizeof(float);  // 199680
    const size_t sm_slice = (24576 + 384 * 33) * sizeof(float);      // 148992
    cudaFuncSetAttribute(k_main,  cudaFuncAttributeMaxDynamicSharedMemorySize, (int)sm_main);
    cudaFuncSetAttribute(k_slice, cudaFuncAttributeMaxDynamicSharedMemorySize, (int)sm_slice);

    // launch index 3 = k_main -> ncu capture target
    k_s1<<<64, 256>>>(x);
    k_contract<<<dim3(256, 2), 256>>>(x);
    k_a1<<<dim3(8, 10), 256>>>();
    k_main<<<148, 256, sm_main>>>(x, W33, b33, out);
    k_a0<<<8, 256>>>();
    k_vec<<<dim3(256, 7), 256>>>(W12, b12, W12t, b12t, W02, b02, W11, b11, W01, b01, b22);
    k_slice<<<768, 256, sm_slice>>>(W22);
    k_scatter<<<256, 256>>>(out);
}

// round 17
// speedup vs baseline: 1.6715x; 1.4314x over previous
#include <cuda_runtime.h>
#include <cuda_bf16.h>

typedef unsigned long long u64;
typedef unsigned int u32;

// tcgen05 only exists in arch-specific ('a'/'f') compilation passes.
#if defined(__CUDA_ARCH_FEAT_SM103_ALL) || defined(__CUDA_ARCH_FEAT_SM100_ALL) || \
    defined(__CUDA_ARCH_SPECIFIC__) || defined(__CUDA_ARCH_FAMILY_SPECIFIC__)
#define HAS_TC 1
#else
#define HAS_TC 0
#endif

static __device__ __forceinline__ u64 pk2(float lo, float hi) {
    u64 r; asm("mov.b64 %0,{%1,%2};" : "=l"(r) : "f"(lo), "f"(hi)); return r;
}
static __device__ __forceinline__ void unpk(u64 v, float &lo, float &hi) {
    asm("mov.b64 {%0,%1}, %2;" : "=f"(lo), "=f"(hi) : "l"(v));
}
static __device__ __forceinline__ void ffma2(u64 &d, u64 a, u64 b) {
    asm("fma.rn.f32x2 %0, %1, %2, %0;" : "+l"(d) : "l"(a), "l"(b));
}

// ---------------- tcgen05 helpers ------------------------------------------
static __device__ __forceinline__ u32 smem_u32(const void* p) {
    u32 a;
    asm("{ .reg .u64 t; cvta.to.shared.u64 t, %1; cvt.u32.u64 %0, t; }" : "=r"(a) : "l"(p));
    return a;
}
#if HAS_TC
static __device__ __forceinline__ u32 elect_one() {
    u32 pred;
    asm volatile("{\n\t.reg .pred p;\n\telect.sync _|p, 0xFFFFFFFF;\n\tselp.b32 %0, 1, 0, p;\n\t}" : "=r"(pred));
    return pred;
}
#define TC_ALLOC(smem_addr, n)  asm volatile("tcgen05.alloc.cta_group::1.sync.aligned.shared::cta.b32 [%0], %1;" :: "r"(smem_addr), "r"((u32)(n)) : "memory")
#define TC_DEALLOC(tmem, n)     asm volatile("tcgen05.dealloc.cta_group::1.sync.aligned.b32 %0, %1;" :: "r"(tmem), "r"((u32)(n)))
#define TC_RELINQ()             asm volatile("tcgen05.relinquish_alloc_permit.cta_group::1.sync.aligned;")
#define TC_COMMIT(mbar)         asm volatile("tcgen05.commit.cta_group::1.mbarrier::arrive::one.shared::cluster.b64 [%0];" :: "r"((u32)(mbar)) : "memory")
#define TC_WAIT_LD()            asm volatile("tcgen05.wait::ld.sync.aligned;" ::: "memory")
#define TC_FENCE_BEFORE()       asm volatile("tcgen05.fence::before_thread_sync;" ::: "memory")
#define TC_FENCE_AFTER()        asm volatile("tcgen05.fence::after_thread_sync;" ::: "memory")
#define FENCE_PROXY_ASYNC()     asm volatile("fence.proxy.async.shared::cta;" ::: "memory")
#define MBAR_INIT(addr, cnt)    asm volatile("mbarrier.init.shared.b64 [%0], %1;" :: "r"((u32)(addr)), "r"((u32)(cnt)) : "memory")
#define MBAR_INVAL(addr)        asm volatile("mbarrier.inval.shared.b64 [%0];" :: "r"((u32)(addr)) : "memory")
#define MBAR_WAIT(addr, par) do { \
    u32 _m = (u32)(addr), _p = (u32)(par), _d; \
    asm volatile("{\n\t.reg .pred p;\n\tmbarrier.try_wait.parity.acquire.cta.shared::cta.b64 p, [%1], %2;\n\tselp.b32 %0, 1, 0, p;\n\t}" \
        : "=r"(_d) : "r"(_m), "r"(_p) : "memory"); \
    if (!_d) { \
        asm volatile("{\n\t.reg .pred P1;\n\tWL_%=:\n\tmbarrier.try_wait.parity.acquire.cta.shared::cta.b64 P1, [%0], %1, 0x989680;\n\t@P1 bra.uni WD_%=;\n\tbra.uni WL_%=;\n\tWD_%=:\n\t}" \
            :: "r"(_m), "r"(_p) : "memory"); \
    } \
} while (0)
#define TC_LD_X32(r, tmem_addr) \
    asm volatile("tcgen05.ld.sync.aligned.32x32b.x32.b32 " \
        "{%0, %1, %2, %3, %4, %5, %6, %7, %8, %9, %10, %11, %12, %13, %14, %15, " \
        "%16, %17, %18, %19, %20, %21, %22, %23, %24, %25, %26, %27, %28, %29, %30, %31}, [%32];" \
        : "=r"((r)[0]), "=r"((r)[1]), "=r"((r)[2]), "=r"((r)[3]), "=r"((r)[4]), "=r"((r)[5]), "=r"((r)[6]), "=r"((r)[7]), \
          "=r"((r)[8]), "=r"((r)[9]), "=r"((r)[10]), "=r"((r)[11]), "=r"((r)[12]), "=r"((r)[13]), "=r"((r)[14]), "=r"((r)[15]), \
          "=r"((r)[16]), "=r"((r)[17]), "=r"((r)[18]), "=r"((r)[19]), "=r"((r)[20]), "=r"((r)[21]), "=r"((r)[22]), "=r"((r)[23]), \
          "=r"((r)[24]), "=r"((r)[25]), "=r"((r)[26]), "=r"((r)[27]), "=r"((r)[28]), "=r"((r)[29]), "=r"((r)[30]), "=r"((r)[31]) \
        : "r"(tmem_addr))

static __device__ __forceinline__ void mma_bf16_ss(u32 d_tmem, u64 a_desc, u64 b_desc, u32 idesc, bool acc) {
    u32 en = acc ? 1u : 0u;
    asm volatile(
        "{\n\t.reg .pred p;\n\tsetp.ne.u32 p, %5, 0;\n\t"
        "tcgen05.mma.cta_group::1.kind::f16 [%0], %1, %2, %3, {%4, %4, %4, %4}, p;\n\t}"
        :: "r"(d_tmem), "l"(a_desc), "l"(b_desc), "r"(idesc), "r"(0u), "r"(en) : "memory");
}
#endif  // HAS_TC

static constexpr u64 DESC_BASE_SW128 =
    (u64(2) << 61) | (u64(1) << 46) | (u64(64) << 32) | (u64(1) << 16);
static __device__ __forceinline__ u64 mk_desc(u32 addr) {
    return DESC_BASE_SW128 | ((u64)(addr >> 4) & 0x3FFF);
}
static __device__ __forceinline__ u32 sw128(u32 b) { return b ^ ((b >> 3) & 0x70); }

// idesc: F32 accum, bf16 x bf16, M=128, N=64 (matches test_mma derivation)
static constexpr u32 MMA_IDESC = (1u << 4) | (1u << 7) | (1u << 10) | (8u << 17) | (8u << 24);

static __device__ __forceinline__ u32 pack_hi_res(float a, float b, float &ra, float &rb) {
    __nv_bfloat16 ha = __float2bfloat16_rn(a), hb = __float2bfloat16_rn(b);
    ra = a - __bfloat162float(ha);
    rb = b - __bfloat162float(hb);
    return (u32)__bfloat16_as_ushort(ha) | ((u32)__bfloat16_as_ushort(hb) << 16);
}
static __device__ __forceinline__ u32 pack_bf2(float a, float b) {
    return (u32)__bfloat16_as_ushort(__float2bfloat16_rn(a)) |
           ((u32)__bfloat16_as_ushort(__float2bfloat16_rn(b)) << 16);
}

// ------------------------------ scratch ------------------------------------
__device__ float g_A2[8 * 32 * 32 * 384];
__device__ float g_A1[8 * 32 * 640];
__device__ float g_A0[8 * 320];
__device__ float g_R12 [3 * 8 * 32 * 64];
__device__ float g_R12t[3 * 8 * 32 * 64];
__device__ float g_R02b[3 * 8 * 64];
__device__ float g_Rmd [8 * 32 * 64];
__device__ float g_S[3 * 8 * 32 * 32 * 64];
__device__ u32 g_Whp[64 * 192];                // W33 hi bf16x2, [o][cc/2]
__device__ u32 g_Wlp[64 * 192];                // W33 lo

// ----------------- K-1: W33 bf16 split (transpose to [o][cc]) ----------------
__global__ void k_wconv(const float* __restrict__ W33) {
    const int idx = blockIdx.x * 256 + threadIdx.x;
    if (idx >= 12288) return;
    const int o = idx / 192, c2 = idx % 192;
    const float w0 = W33[(c2 * 2 + 0) * 64 + o];
    const float w1 = W33[(c2 * 2 + 1) * 64 + o];
    float l0, l1;
    g_Whp[idx] = pack_hi_res(w0, w1, l0, l1);
    g_Wlp[idx] = pack_bf2(l0, l1);
}

// ----------------- K0: s1 contraction, coalesced -----------------------------
__global__ void k_s1(const float* __restrict__ x) {
    const int b = blockIdx.x >> 3, js = blockIdx.x & 7;
    const int tid = threadIdx.x;
    const float4* x4 = (const float4*)x;
    float4 acc[8];
#pragma unroll
    for (int r = 0; r < 8; r++) acc[r] = make_float4(0.f, 0.f, 0.f, 0.f);
    for (int i = 0; i < 32; i++) {
        const float4* base = x4 + b * 524288 + i * 16384 + js * 2048;
#pragma unroll
        for (int r = 0; r < 8; r++) {
            const float4 v = base[r * 256 + tid];
            acc[r].x += v.x; acc[r].y += v.y; acc[r].z += v.z; acc[r].w += v.w;
        }
    }
    float4* A24 = (float4*)g_A2;
#pragma unroll
    for (int r = 0; r < 8; r++) {
        const int f = r * 256 + tid;
        const int jj = f >> 9, rem = f & 511, k = rem >> 4, c4 = rem & 15;
        const int j = js * 4 + jj;
        float4 v;
        v.x = acc[r].x * 0.03125f; v.y = acc[r].y * 0.03125f;
        v.z = acc[r].z * 0.03125f; v.w = acc[r].w * 0.03125f;
        A24[((b * 32 + j) * 32 + k) * 96 + c4] = v;
    }
}

// ----------------- K1: s2+s3 fused pass, diagonals ---------------------------
__global__ void k_contract(const float* __restrict__ x) {
    const int y = blockIdx.y;
    const int b = blockIdx.x >> 5, P = blockIdx.x & 31;
    const int tid = threadIdx.x;
    const float* xb = x + b * 2097152;
    if (y == 0) {
        __shared__ float ps3[4 * 32 * 64];
        const int c = tid & 63, qs = tid >> 6;
        float s2acc[8] = {0, 0, 0, 0, 0, 0, 0, 0};
        const float* base = xb + P * 65536;
        for (int j = 0; j < 32; j++) {
            float t = 0.f;
#pragma unroll
            for (int kk = 0; kk < 8; kk++) {
                const int k = qs + kk * 4;
                const float v = base[j * 2048 + k * 64 + c];
                s2acc[kk] += v; t += v;
            }
            ps3[(qs * 32 + j) * 64 + c] = t;
        }
        __syncthreads();
#pragma unroll
        for (int kk = 0; kk < 8; kk++) {
            const int k = qs + kk * 4;
            g_A2[((b * 32 + P) * 32 + k) * 384 + 64 + c] = s2acc[kk] * 0.03125f;
        }
        for (int idx = tid; idx < 2048; idx += 256) {
            const int j = idx >> 6, cc = idx & 63;
            const float s = ps3[j * 64 + cc] + ps3[2048 + j * 64 + cc]
                          + ps3[4096 + j * 64 + cc] + ps3[6144 + j * 64 + cc];
            g_A2[((b * 32 + P) * 32 + j) * 384 + 128 + cc] = s * 0.03125f;
        }
    } else {
        for (int idx = tid; idx < 6144; idx += 256) {
            const int kind = idx >> 11;
            const int e = (idx >> 6) & 31, c = idx & 63;
            float v;
            if (kind == 0)      v = xb[e * 65536 + e * 2048 + P * 64 + c];
            else if (kind == 1) v = xb[e * 65536 + P * 2048 + e * 64 + c];
            else                v = xb[P * 65536 + e * 2048 + e * 64 + c];
            g_A2[((b * 32 + P) * 32 + e) * 384 + (3 + kind) * 64 + c] = v;
        }
    }
}

// ----------------- K3: main GEMM ---------------------------------------------
// tcgen05 path (arch-specific pass): tile = 4 pencils, M=128, N=64, K=384 in
// 3 chunks of 128; D = Ah*Wh + Ah*Wl + Al*Wh (bf16 3-split), fp32 in TMEM.
// Fallback (non-'a' pass): R13 fp32 f32x2 GEMM.
__global__ void __launch_bounds__(256, 1)
k_main(const float* __restrict__ x, const float* __restrict__ W33,
       const float* __restrict__ b33, float* __restrict__ out) {
    extern __shared__ char dsm[];
#if HAS_TC
    (void)W33;
    __shared__ u32 tmem_ptr_sh;
    __shared__ alignas(8) u64 mbarA, mbarB;
    __shared__ float bsh[64];

    const int tid = threadIdx.x;
    const int warp = tid >> 5, lane = tid & 31;

    const u32 sb = smem_u32(dsm);
    const u32 tileBase = (sb + 1023) & ~1023u;
    char* tp = dsm + (tileBase - sb);
    const u32 OFF_BH = 0, OFF_BL = 49152, OFF_A0 = 98304, OFF_A1 = 163840;
    const u32 mbA = smem_u32(&mbarA), mbB = smem_u32(&mbarB);

    if (warp == 0) TC_ALLOC(smem_u32(&tmem_ptr_sh), 128);
    if (tid == 0) { MBAR_INIT(mbA, 1); MBAR_INIT(mbB, 1); }
    if (tid < 64) bsh[tid] = b33[tid];

    // stage B tiles (Wh, Wl): [n=o][k=cc], 8x64bf16 atoms (atom_col stride = 8 atoms), SW128
    for (int idx = tid; idx < 12288; idx += 256) {
        const int o = idx / 192, c2 = idx % 192;
        const int k0 = c2 * 2;
        const u32 byte = (u32)((o >> 3) + (k0 >> 6) * 8) * 1024 + (o & 7) * 128 + (k0 & 63) * 2;
        const u32 sw = sw128(byte);
        *(u32*)(tp + OFF_BH + sw) = g_Whp[idx];
        *(u32*)(tp + OFF_BL + sw) = g_Wlp[idx];
    }
    __syncthreads();
    const u32 tmem = tmem_ptr_sh;
    if (warp == 0) TC_RELINQ();

    const float4* x4 = (const float4*)x;
    float4* out4 = (float4*)out;

    const u64 bdh = mk_desc(tileBase + OFF_BH);
    const u64 bdl = mk_desc(tileBase + OFF_BL);

    int phA = 0, phB = 0;

    for (int t = blockIdx.x; t < 2048; t += 148) {
        const int pen0 = t * 4;
        const int b = pen0 >> 10, i = (pen0 >> 5) & 31, j0 = pen0 & 31;

#pragma unroll
        for (int chunk = 0; chunk < 3; chunk++) {
            const u32 abuf = (chunk == 1) ? OFF_A1 : OFF_A0;
            if (chunk == 2) { MBAR_WAIT(mbA, phA); phA ^= 1; }   // buf0 free

            for (int idx = tid; idx < 4096; idx += 256) {
                const int lp = idx >> 10;
                const int pp = (idx >> 9) & 1;
                const int p = chunk * 2 + pp;
                const int rem = idx & 511;
                const int k = rem >> 4, c4 = rem & 15;
                const int j = j0 + lp;
                int A, B, C;
                switch (p) {
                    case 0: A = i; B = j; C = k; break;
                    case 1: A = i; B = k; C = j; break;
                    case 2: A = j; B = i; C = k; break;
                    case 3: A = k; B = i; C = j; break;
                    case 4: A = j; B = k; C = i; break;
                    default: A = k; B = j; C = i; break;
                }
                const float4 v = x4[b * 524288 + A * 16384 + B * 512 + C * 16 + c4];
                float lx, ly, lz, lw;
                const u32 h01 = pack_hi_res(v.x, v.y, lx, ly);
                const u32 h23 = pack_hi_res(v.z, v.w, lz, lw);
                const u32 l01 = pack_bf2(lx, ly);
                const u32 l23 = pack_bf2(lz, lw);
                const int row = lp * 32 + k;
                const int col = pp * 64 + c4 * 4;
                const u32 byte = (u32)((row >> 3) + (col >> 6) * 16) * 1024
                               + (row & 7) * 128 + (col & 63) * 2;
                const u32 sw = sw128(byte);
                *(uint2*)(tp + abuf + sw)         = make_uint2(h01, h23);
                *(uint2*)(tp + abuf + 32768 + sw) = make_uint2(l01, l23);
            }
            __syncthreads();

            if (warp == 0 && elect_one()) {
                FENCE_PROXY_ASYNC();
                const u64 adh = mk_desc(tileBase + abuf);
                const u64 adl = mk_desc(tileBase + abuf + 32768);
                bool en = (chunk != 0);
#pragma unroll
                for (int prod = 0; prod < 3; prod++) {
                    const u64 ab = (prod == 2) ? adl : adh;
                    const u64 bb = (prod == 1) ? bdl : bdh;
#pragma unroll
                    for (int s = 0; s < 8; s++) {
                        const u64 ao = (u64)((s >> 2) << 10) + ((s & 3) << 1);
                        const u64 bo = (u64)(2 * chunk + (s >> 2)) * 512 + ((s & 3) << 1);
                        mma_bf16_ss(tmem, ab + ao, bb + bo, MMA_IDESC, en);
                        en = true;
                    }
                }
                if (chunk == 1) TC_COMMIT(mbA);
                if (chunk == 2) TC_COMMIT(mbB);
            }
        }

        MBAR_WAIT(mbB, phB); phB ^= 1;
        TC_FENCE_AFTER();

        if (warp < 4) {
            u32 d[64];
            TC_LD_X32(d, tmem);
            TC_LD_X32(d + 32, tmem + 32);
            TC_WAIT_LD();
            TC_FENCE_BEFORE();
            const int pen = pen0 + warp;
            const int ob = pen * 512 + lane * 16;
#pragma unroll
            for (int c4 = 0; c4 < 16; c4++) {
                float4 r;
                r.x = __uint_as_float(d[c4 * 4 + 0]) + bsh[c4 * 4 + 0];
                r.y = __uint_as_float(d[c4 * 4 + 1]) + bsh[c4 * 4 + 1];
                r.z = __uint_as_float(d[c4 * 4 + 2]) + bsh[c4 * 4 + 2];
                r.w = __uint_as_float(d[c4 * 4 + 3]) + bsh[c4 * 4 + 3];
                out4[ob + c4] = r;
            }
        }
        __syncthreads();
    }

    __syncthreads();
    if (tid == 0) { MBAR_INVAL(mbA); MBAR_INVAL(mbB); }
    __syncthreads();
    if (warp == 0) TC_DEALLOC(tmem, 128);
#else
    // ---------------- fp32 fallback (R13 body) ----------------
    float* sm = (float*)dsm;
    float* wsh  = sm;
    float* xshA = sm + 24576;
    float* xshB = sm + 24576 + 12672;
    const int tid = threadIdx.x;
    const int warp = tid >> 5, lane = tid & 31;
    const int o0 = warp * 8;

    const float4* W4 = (const float4*)W33;
    float4* wsh4 = (float4*)wsh;
    for (int idx = tid; idx < 6144; idx += 256) wsh4[idx] = W4[idx];

    const float4* x4 = (const float4*)x;
    float4* out4 = (float4*)out;

    const u64 bi0 = pk2(__ldg(b33 + o0 + 0), __ldg(b33 + o0 + 1));
    const u64 bi1 = pk2(__ldg(b33 + o0 + 2), __ldg(b33 + o0 + 3));
    const u64 bi2 = pk2(__ldg(b33 + o0 + 4), __ldg(b33 + o0 + 5));
    const u64 bi3 = pk2(__ldg(b33 + o0 + 6), __ldg(b33 + o0 + 7));

    __syncthreads();

    for (int pr = blockIdx.x; pr < 2112; pr += gridDim.x) {
        const int u0 = pr * 2, u1 = pr * 2 + 1;
        const int b0 = u0 / 528; int r0 = u0 - b0 * 528;
        int i0 = 0; while (r0 >= 32 - i0) { r0 -= 32 - i0; i0++; }
        const int j0 = i0 + r0;
        const int b1 = u1 / 528; int r1 = u1 - b1 * 528;
        int i1 = 0; while (r1 >= 32 - i1) { r1 -= 32 - i1; i1++; }
        const int j1 = i1 + r1;

        for (int idx = tid; idx < 6144; idx += 256) {
            const int h = idx / 3072;
            const int id2 = idx - h * 3072;
            const int p = id2 >> 9, rem = id2 & 511, k = rem >> 4, c4 = rem & 15;
            const int bb = h ? b1 : b0, i = h ? i1 : i0, j = h ? j1 : j0;
            int A, B, C;
            switch (p) {
                case 0: A = i; B = j; C = k; break;
                case 1: A = i; B = k; C = j; break;
                case 2: A = j; B = i; C = k; break;
                case 3: A = k; B = i; C = j; break;
                case 4: A = j; B = k; C = i; break;
                default: A = k; B = j; C = i; break;
            }
            const float4 v = x4[bb * 524288 + A * 16384 + B * 512 + C * 16 + c4];
            float* dst = h ? xshB : xshA;
            const int cc = p * 64 + c4 * 4;
            dst[(cc + 0) * 33 + k] = v.x;
            dst[(cc + 1) * 33 + k] = v.y;
            dst[(cc + 2) * 33 + k] = v.z;
            dst[(cc + 3) * 33 + k] = v.w;
        }
        __syncthreads();

        u64 aA0 = bi0, aA1 = bi1, aA2 = bi2, aA3 = bi3;
        u64 aB0 = bi0, aB1 = bi1, aB2 = bi2, aB3 = bi3;
        u64 aC0 = bi0, aC1 = bi1, aC2 = bi2, aC3 = bi3;
        u64 aD0 = bi0, aD1 = bi1, aD2 = bi2, aD3 = bi3;
        const int map1[6] = {2, 4, 0, 5, 1, 3};
#pragma unroll
        for (int p = 0; p < 6; p++) {
            const float* xA = xshA + p * 2112;
            const float* xB = xshA + map1[p] * 2112;
            const float* xC = xshB + p * 2112;
            const float* xD = xshB + map1[p] * 2112;
            const float* wp = wsh + (p << 12) + o0;
#pragma unroll 8
            for (int c = 0; c < 64; c++) {
                const ulonglong2* wr = (const ulonglong2*)(wp + c * 64);
                const ulonglong2 wv0 = wr[0];
                const ulonglong2 wv1 = wr[1];
                const int xo = c * 33 + lane;
                const u64 va = pk2(xA[xo], xA[xo]);
                const u64 vb = pk2(xB[xo], xB[xo]);
                const u64 vc = pk2(xC[xo], xC[xo]);
                const u64 vd = pk2(xD[xo], xD[xo]);
                ffma2(aA0, va, wv0.x); ffma2(aA1, va, wv0.y);
                ffma2(aA2, va, wv1.x); ffma2(aA3, va, wv1.y);
                ffma2(aB0, vb, wv0.x); ffma2(aB1, vb, wv0.y);
                ffma2(aB2, vb, wv1.x); ffma2(aB3, vb, wv1.y);
                ffma2(aC0, vc, wv0.x); ffma2(aC1, vc, wv0.y);
                ffma2(aC2, vc, wv1.x); ffma2(aC3, vc, wv1.y);
                ffma2(aD0, vd, wv0.x); ffma2(aD1, vd, wv0.y);
                ffma2(aD2, vd, wv1.x); ffma2(aD3, vd, wv1.y);
            }
        }
        float4 r0v, r1v;
        unpk(aA0, r0v.x, r0v.y); unpk(aA1, r0v.z, r0v.w);
        unpk(aA2, r1v.x, r1v.y); unpk(aA3, r1v.z, r1v.w);
        int ob = ((b0 * 32 + i0) * 32 + j0) * 512 + lane * 16 + (o0 >> 2);
        out4[ob] = r0v; out4[ob + 1] = r1v;
        if (i0 != j0) {
            unpk(aB0, r0v.x, r0v.y); unpk(aB1, r0v.z, r0v.w);
            unpk(aB2, r1v.x, r1v.y); unpk(aB3, r1v.z, r1v.w);
            ob = ((b0 * 32 + j0) * 32 + i0) * 512 + lane * 16 + (o0 >> 2);
            out4[ob] = r0v; out4[ob + 1] = r1v;
        }
        unpk(aC0, r0v.x, r0v.y); unpk(aC1, r0v.z, r0v.w);
        unpk(aC2, r1v.x, r1v.y); unpk(aC3, r1v.z, r1v.w);
        ob = ((b1 * 32 + i1) * 32 + j1) * 512 + lane * 16 + (o0 >> 2);
        out4[ob] = r0v; out4[ob + 1] = r1v;
        if (i1 != j1) {
            unpk(aD0, r0v.x, r0v.y); unpk(aD1, r0v.z, r0v.w);
            unpk(aD2, r1v.x, r1v.y); unpk(aD3, r1v.z, r1v.w);
            ob = ((b1 * 32 + j1) * 32 + i1) * 512 + lane * 16 + (o0 >> 2);
            out4[ob] = r0v; out4[ob + 1] = r1v;
        }
        __syncthreads();
    }
#endif
}

// ----------------- K2: a1 from A2. grid (8, 10), 256 threads ----------------
__global__ void k_a1() {
    const int b = blockIdx.x, blk = blockIdx.y;
    const int tid = threadIdx.x;
    const int t = tid >> 3, c0 = (tid & 7) * 8;
    int off, axis;
    switch (blk) {
        case 0: off = 0;   axis = 0; break;
        case 1: off = 0;   axis = 1; break;
        case 2: off = 64;  axis = 1; break;
        case 3: off = 192; axis = 0; break;
        case 4: off = 192; axis = 1; break;
        case 5: off = 256; axis = 0; break;
        case 6: off = 256; axis = 1; break;
        case 7: off = 320; axis = 0; break;
        case 8: off = 320; axis = 1; break;
        default: off = 320; axis = 2; break;
    }
#pragma unroll
    for (int e = 0; e < 8; e++) {
        const int c = c0 + e;
        float s = 0.f;
        if (axis == 2) {
            s = g_A2[((b * 32 + t) * 32 + t) * 384 + off + c];
        } else if (axis == 0) {
            for (int p = 0; p < 32; p++) s += g_A2[((b * 32 + p) * 32 + t) * 384 + off + c];
            s *= 0.03125f;
        } else {
            for (int q = 0; q < 32; q++) s += g_A2[((b * 32 + t) * 32 + q) * 384 + off + c];
            s *= 0.03125f;
        }
        g_A1[(b * 32 + t) * 640 + blk * 64 + c] = s;
    }
}

// ----------------- K2b: a0 from a1. grid 8, 256 threads ---------------------
__global__ void k_a0() {
    const int b = blockIdx.x;
    const int srcmap[5] = {2, 4, 6, 8, 9};
    for (int idx = threadIdx.x; idx < 320; idx += 256) {
        const int blk = idx >> 6, c = idx & 63;
        const int so = srcmap[blk] * 64 + c;
        float s = 0.f;
        for (int t = 0; t < 32; t++) s += g_A1[(b * 32 + t) * 640 + so];
        g_A0[b * 320 + idx] = s * 0.03125f;
    }
}

// ----------------- K4: vector mixes. grid (256, 7), 256 threads -------------
__global__ void k_vec(const float* __restrict__ W12, const float* __restrict__ b12,
                      const float* __restrict__ W12t, const float* __restrict__ b12t,
                      const float* __restrict__ W02, const float* __restrict__ b02,
                      const float* __restrict__ W11, const float* __restrict__ b11,
                      const float* __restrict__ W01, const float* __restrict__ b01,
                      const float* __restrict__ b22) {
    __shared__ float a1sh[640];
    __shared__ float a0sh[320];
    __shared__ float psum[4][64];
    __shared__ float psum2[4][64];
    const int row = blockIdx.x;
    const int y = blockIdx.y;
    const int tid = threadIdx.x;
    const int o = tid & 63, chunk = tid >> 6;
    const int b = row >> 5, t = row & 31;

    for (int idx = tid; idx < 640; idx += 256) a1sh[idx] = g_A1[row * 640 + idx];
    if (y == 6) for (int idx = tid; idx < 320; idx += 256) a0sh[idx] = g_A0[b * 320 + idx];
    __syncthreads();

    const float* W; float* dst;
    if (y < 3)      { W = W12  + y * 40960;        dst = g_R12  + (y * 256 + row) * 64; }
    else if (y < 6) { W = W12t + (y - 3) * 40960;  dst = g_R12t + ((y - 3) * 256 + row) * 64; }
    else            { W = W11;                     dst = g_Rmd + row * 64; }

    float acc = 0.f;
    const int k0 = chunk * 160;
#pragma unroll 8
    for (int k = k0; k < k0 + 160; k++)
        acc += a1sh[k] * __ldg(W + k * 64 + o);
    if (y == 6) {
#pragma unroll 8
        for (int k = chunk * 80; k < chunk * 80 + 80; k++)
            acc += a0sh[k] * __ldg(W01 + k * 64 + o);
    }
    psum[chunk][o] = acc;

    if (y == 6 && t < 3) {
        float acc2 = 0.f;
#pragma unroll 8
        for (int k = chunk * 80; k < chunk * 80 + 80; k++)
            acc2 += a0sh[k] * __ldg(W02 + t * 20480 + k * 64 + o);
        psum2[chunk][o] = acc2;
    }
    __syncthreads();
    if (chunk == 0) {
        float s = psum[0][o] + psum[1][o] + psum[2][o] + psum[3][o];
        if (y < 3)      s += __ldg(b12  + y * 64 + o);
        else if (y < 6) s += __ldg(b12t + (y - 3) * 64 + o);
        else            s += __ldg(b11 + o) + __ldg(b01 + o);
        dst[o] = s;
        if (y == 6 && t < 3) {
            float s2 = psum2[0][o] + psum2[1][o] + psum2[2][o] + psum2[3][o]
                     + __ldg(b02 + t * 64 + o) + __ldg(b22 + t * 64 + o);
            g_R02b[(t * 8 + b) * 64 + o] = s2;
        }
    }
}

// ----------------- K5: slice GEMM  slices[i] = a2wt @ W22[i] + terms --------
__global__ void k_slice(const float* __restrict__ W22) {
    extern __shared__ float sm[];
    float* wsh = sm;
    float* ash = sm + 24576;
    const int bid = blockIdx.x;
    const int i = bid >> 8, b = (bid >> 5) & 7, t = bid & 31;
    const int tid = threadIdx.x;
    const int warp = tid >> 5, lane = tid & 31;
    const int o0 = warp * 8;

    float bo[8];
#pragma unroll
    for (int e = 0; e < 8; e++) {
        const int o = o0 + e;
        bo[e] = g_R12[((i * 8 + b) * 32 + t) * 64 + o]
              + g_R12t[((i * 8 + b) * 32 + lane) * 64 + o]
              + g_R02b[(i * 8 + b) * 64 + o];
    }
    u64 acc0 = pk2(bo[0], bo[1]), acc1 = pk2(bo[2], bo[3]);
    u64 acc2 = pk2(bo[4], bo[5]), acc3 = pk2(bo[6], bo[7]);

    const float4* W4 = (const float4*)(W22 + i * 49152);
    const float4* A24 = (const float4*)g_A2;

    for (int tile = 0; tile < 2; tile++) {
        for (int idx = tid; idx < 6144; idx += 256)
            ((float4*)wsh)[idx] = W4[tile * 6144 + idx];
        for (int idx = tid; idx < 3072; idx += 256) {
            const int d = idx / 96, c4 = idx % 96;
            const int P = tile ? d : t, Q = tile ? t : d;
            const float4 v = A24[((b * 32 + P) * 32 + Q) * 96 + c4];
            const int cc = c4 * 4;
            ash[(cc + 0) * 33 + d] = v.x;
            ash[(cc + 1) * 33 + d] = v.y;
            ash[(cc + 2) * 33 + d] = v.z;
            ash[(cc + 3) * 33 + d] = v.w;
        }
        __syncthreads();
#pragma unroll 4
        for (int cc = 0; cc < 384; cc++) {
            const ulonglong2* wr = (const ulonglong2*)(wsh + cc * 64 + o0);
            const ulonglong2 wv0 = wr[0];
            const ulonglong2 wv1 = wr[1];
            const float xv = ash[cc * 33 + lane];
            const u64 xx = pk2(xv, xv);
            ffma2(acc0, xx, wv0.x); ffma2(acc1, xx, wv0.y);
            ffma2(acc2, xx, wv1.x); ffma2(acc3, xx, wv1.y);
        }
        __syncthreads();
    }
    float4 r0, r1;
    unpk(acc0, r0.x, r0.y); unpk(acc1, r0.z, r0.w);
    unpk(acc2, r1.x, r1.y); unpk(acc3, r1.z, r1.w);
    float4* S4 = (float4*)g_S;
    const int ob = (((i * 8 + b) * 32 + t) * 32 + lane) * 16 + (o0 >> 2);
    S4[ob] = r0; S4[ob + 1] = r1;
}

// ----------------- K6: diagonal scatter-add. grid 256, 256 threads ----------
__global__ void k_scatter(float* __restrict__ out) {
    const int bt = blockIdx.x;
    const int b = bt >> 5, t = bt & 31;
    const int tid = threadIdx.x;
    const int dg = tid >> 6, c = tid & 63;
    const float* S0 = g_S + ((0 * 8 + b) * 32 + t) * 2048;
    const float* S1 = g_S + ((1 * 8 + b) * 32 + t) * 2048;
    const float* S2 = g_S + ((2 * 8 + b) * 32 + t) * 2048;
    float* ob = out + b * 2097152;
    for (int d = dg; d < 32; d += 4) {
        const float s0 = S0[d * 64 + c], s1 = S1[d * 64 + c], s2 = S2[d * 64 + c];
        if (d != t) {
            ob[d * 65536 + d * 2048 + t * 64 + c] += s0;   // T[b,d,d,t]
            ob[d * 65536 + t * 2048 + d * 64 + c] += s1;   // T[b,d,t,d]
            ob[t * 65536 + d * 2048 + d * 64 + c] += s2;   // T[b,t,d,d]
        } else {
            ob[d * 65536 + d * 2048 + d * 64 + c] += s0 + s1 + s2 + g_Rmd[(b * 32 + d) * 64 + c];
        }
    }
}

// ---------------------------------------------------------------------------
extern "C" void kernel_launch(void* const* d_in, const int* in_sizes, int n_in,
                              void* d_out, int out_size) {
    const float* x    = (const float*)d_in[0];
    const float* W33  = (const float*)d_in[1];
    const float* b33  = (const float*)d_in[2];
    const float* W22  = (const float*)d_in[3];
    const float* b22  = (const float*)d_in[4];
    const float* W12  = (const float*)d_in[5];
    const float* b12  = (const float*)d_in[6];
    const float* W12t = (const float*)d_in[7];
    const float* b12t = (const float*)d_in[8];
    const float* W02  = (const float*)d_in[9];
    const float* b02  = (const float*)d_in[10];
    const float* W11  = (const float*)d_in[11];
    const float* b11  = (const float*)d_in[12];
    const float* W01  = (const float*)d_in[13];
    const float* b01  = (const float*)d_in[14];
    float* out = (float*)d_out;

    const size_t sm_main  = 230400;
    const size_t sm_slice = (24576 + 384 * 33) * sizeof(float);  // 148992
    cudaFuncSetAttribute(k_main,  cudaFuncAttributeMaxDynamicSharedMemorySize, (int)sm_main);
    cudaFuncSetAttribute(k_slice, cudaFuncAttributeMaxDynamicSharedMemorySize, (int)sm_slice);

    // launch index 3 = k_main -> ncu capture target
    k_wconv<<<48, 256>>>(W33);
    k_s1<<<64, 256>>>(x);
    k_contract<<<dim3(256, 2), 256>>>(x);
    k_main<<<148, 256, sm_main>>>(x, W33, b33, out);
    k_a1<<<dim3(8, 10), 256>>>();
    k_a0<<<8, 256>>>();
    k_vec<<<dim3(256, 7), 256>>>(W12, b12, W12t, b12t, W02, b02, W11, b11, W01, b01, b22);
    k_slice<<<768, 256, sm_slice>>>(W22);
    k_scatter<<<256, 256>>>(out);
}